// round 3
// baseline (speedup 1.0000x reference)
#include <cuda_runtime.h>

// ---------------------------------------------------------------------------
// BERT attention block, fp32 baseline using packed f32x2 FMA (sm_103a FFMA2).
//   B=2, L=2048, H=1024, NH=16, D=64
//   q = E@Wq+bq; k = E@Wk+bk; v = E@Wv+bv   (per-head split)
//   S = (Q @ V^T)/4 + mask ; P = softmax(S) ; A = P @ K   (reference's swap!)
//   O = A @ Wo + bo + E ; out = LayerNorm(O)*gamma + beta
// ---------------------------------------------------------------------------

typedef unsigned long long u64;

__device__ __forceinline__ u64 pack2(float lo, float hi) {
    u64 r; asm("mov.b64 %0, {%1, %2};" : "=l"(r) : "f"(lo), "f"(hi)); return r;
}
__device__ __forceinline__ float2 unpack2(u64 v) {
    float2 f; asm("mov.b64 {%0, %1}, %2;" : "=f"(f.x), "=f"(f.y) : "l"(v)); return f;
}
__device__ __forceinline__ void ffma2(u64& d, u64 a, u64 b) {
    asm("fma.rn.f32x2 %0, %1, %2, %0;" : "+l"(d) : "l"(a), "l"(b));
}
__device__ __forceinline__ void fmul2(u64& d, u64 s) {
    asm("mul.rn.f32x2 %0, %0, %1;" : "+l"(d) : "l"(s));
}

#define MDIM 4096
#define NDIM 1024
#define KDIM 1024
#define LSEQ 2048
#define NHEADS 16
#define HEADD 64

// scratch (allocation-free rule: __device__ globals)
__device__ float g_q[MDIM * NDIM];
__device__ float g_k[MDIM * NDIM];
__device__ float g_v[MDIM * NDIM];
__device__ float g_att[MDIM * NDIM];
__device__ float g_o[MDIM * NDIM];

// ---------------------------------------------------------------------------
// Tiled SGEMM: out = X[M,K] @ W[K,N] + bias (+ resid). BM=BN=128, BK=8,
// 256 threads, 8x8 microtile done as 8x4 packed f32x2 FMAs.
// blockIdx.z selects among up to 3 (W, bias, out) triples (fused QKV).
// ---------------------------------------------------------------------------
__global__ __launch_bounds__(256, 2)
void gemm_bias_kernel(const float* __restrict__ X,
                      const float* __restrict__ W0, const float* __restrict__ W1,
                      const float* __restrict__ W2,
                      const float* __restrict__ b0, const float* __restrict__ b1,
                      const float* __restrict__ b2,
                      float* __restrict__ O0, float* __restrict__ O1,
                      float* __restrict__ O2,
                      const float* __restrict__ resid)
{
    const float* W; const float* bias; float* O;
    if (blockIdx.z == 0)      { W = W0; bias = b0; O = O0; }
    else if (blockIdx.z == 1) { W = W1; bias = b1; O = O1; }
    else                      { W = W2; bias = b2; O = O2; }

    __shared__ float As[8][132];   // A tile, k-major (transposed), padded
    __shared__ float Bs[8][128];   // B tile, k-major

    const int tid  = threadIdx.x;
    const int m0   = blockIdx.y * 128;
    const int n0   = blockIdx.x * 128;
    const int arow = tid >> 1;            // 0..127
    const int acol = (tid & 1) * 4;       // 0 or 4
    const int brow = tid >> 5;            // 0..7
    const int bcol = (tid & 31) * 4;      // 0..124
    const int tx   = tid & 15;
    const int ty   = tid >> 4;

    const float* Aptr = X + (size_t)(m0 + arow) * KDIM + acol;
    const float* Bptr = W + (size_t)brow * NDIM + n0 + bcol;

    u64 acc[8][4];
#pragma unroll
    for (int i = 0; i < 8; i++)
#pragma unroll
        for (int j = 0; j < 4; j++) acc[i][j] = 0ull;

    for (int k0 = 0; k0 < KDIM; k0 += 8) {
        float4 av = *(const float4*)(Aptr + k0);
        float4 bv = *(const float4*)(Bptr + (size_t)k0 * NDIM);
        __syncthreads();
        As[acol + 0][arow] = av.x;
        As[acol + 1][arow] = av.y;
        As[acol + 2][arow] = av.z;
        As[acol + 3][arow] = av.w;
        *(float4*)&Bs[brow][bcol] = bv;
        __syncthreads();
#pragma unroll
        for (int kk = 0; kk < 8; kk++) {
            float4 a0 = *(const float4*)&As[kk][ty * 4];
            float4 a1 = *(const float4*)&As[kk][ty * 4 + 64];
            float4 c0 = *(const float4*)&Bs[kk][tx * 4];
            float4 c1 = *(const float4*)&Bs[kk][tx * 4 + 64];
            u64 bp[4] = { pack2(c0.x, c0.y), pack2(c0.z, c0.w),
                          pack2(c1.x, c1.y), pack2(c1.z, c1.w) };
            float am[8] = { a0.x, a0.y, a0.z, a0.w, a1.x, a1.y, a1.z, a1.w };
#pragma unroll
            for (int i = 0; i < 8; i++) {
                u64 ap = pack2(am[i], am[i]);
#pragma unroll
                for (int j = 0; j < 4; j++) ffma2(acc[i][j], ap, bp[j]);
            }
        }
    }

#pragma unroll
    for (int i = 0; i < 8; i++) {
        int r = m0 + ty * 4 + (i & 3) + (i >> 2) * 64;
#pragma unroll
        for (int h2 = 0; h2 < 2; h2++) {
            int c = n0 + h2 * 64 + tx * 4;
            float2 p0 = unpack2(acc[i][h2 * 2 + 0]);
            float2 p1 = unpack2(acc[i][h2 * 2 + 1]);
            float4 bb = *(const float4*)&bias[c];
            float4 o;
            o.x = p0.x + bb.x; o.y = p0.y + bb.y;
            o.z = p1.x + bb.z; o.w = p1.y + bb.w;
            if (resid) {
                float4 rv = *(const float4*)&resid[(size_t)r * NDIM + c];
                o.x += rv.x; o.y += rv.y; o.z += rv.z; o.w += rv.w;
            }
            *(float4*)&O[(size_t)r * NDIM + c] = o;
        }
    }
}

// ---------------------------------------------------------------------------
// Flash attention per (b, head, 64-query tile). 64-wide K/V tiles.
//   S = Q @ V^T / 4 + mask ; online softmax ; acc += P @ K.
// smem: Qs [d][i] (16KB), VPs aliased V-tile[d][j] / P-tile[i][j] (16KB),
//       Ks [j][d] (16KB) = 48KB static.
// ---------------------------------------------------------------------------
__global__ __launch_bounds__(256, 2)
void flash_attn_kernel(const float* __restrict__ Qg, const float* __restrict__ Kg,
                       const float* __restrict__ Vg, const float* __restrict__ maskg,
                       float* __restrict__ Og)
{
    __shared__ float Qs[64 * 64];    // Qs[d][i]
    __shared__ float VPs[64 * 64];   // phase A: Vs[d][j]; phase B: Ps[i][j]
    __shared__ float Ks[64 * 64];    // Ks[j][d]

    const int tid = threadIdx.x;
    const int tx  = tid & 15;        // 16 col groups (x4)
    const int ty  = tid >> 4;        // 16 row groups (x4)
    const int bh  = blockIdx.y;
    const int b   = bh >> 4;
    const int h   = bh & 15;
    const int q0  = blockIdx.x * 64;

    const int li  = tid >> 2;        // row 0..63 for tile loads
    const int ld0 = (tid & 3) * 16;  // 16 d-elems per thread

    // load Q tile transposed: Qs[d][i]
    {
        const float* qp = Qg + (size_t)(b * LSEQ + q0 + li) * NDIM + h * HEADD + ld0;
#pragma unroll
        for (int u = 0; u < 4; u++) {
            float4 v = *(const float4*)(qp + u * 4);
            int d = ld0 + u * 4;
            Qs[(d + 0) * 64 + li] = v.x;
            Qs[(d + 1) * 64 + li] = v.y;
            Qs[(d + 2) * 64 + li] = v.z;
            Qs[(d + 3) * 64 + li] = v.w;
        }
    }

    float mrow[4], lrow[4];
    u64 acc[4][2];
#pragma unroll
    for (int i = 0; i < 4; i++) {
        mrow[i] = -1e30f; lrow[i] = 0.f; acc[i][0] = 0ull; acc[i][1] = 0ull;
    }

    for (int kt = 0; kt < 32; kt++) {
        const int k0 = kt * 64;
        const float* kp = Kg + (size_t)(b * LSEQ + k0 + li) * NDIM + h * HEADD + ld0;
        const float* vp = Vg + (size_t)(b * LSEQ + k0 + li) * NDIM + h * HEADD + ld0;

        __syncthreads();   // previous iteration done with VPs / Ks
#pragma unroll
        for (int u = 0; u < 4; u++) {
            float4 v = *(const float4*)(vp + u * 4);
            int d = ld0 + u * 4;
            VPs[(d + 0) * 64 + li] = v.x;
            VPs[(d + 1) * 64 + li] = v.y;
            VPs[(d + 2) * 64 + li] = v.z;
            VPs[(d + 3) * 64 + li] = v.w;
            float4 kv = *(const float4*)(kp + u * 4);
            *(float4*)&Ks[li * 64 + ld0 + u * 4] = kv;
        }
        __syncthreads();

        // GEMM1: s[i][j] = sum_d Qs[d][i] * Vs[d][j]
        u64 s2[4][2];
#pragma unroll
        for (int i = 0; i < 4; i++) { s2[i][0] = 0ull; s2[i][1] = 0ull; }
#pragma unroll 8
        for (int d = 0; d < 64; d++) {
            float4 a  = *(const float4*)&Qs[d * 64 + ty * 4];
            float4 bb = *(const float4*)&VPs[d * 64 + tx * 4];
            u64 bp0 = pack2(bb.x, bb.y), bp1 = pack2(bb.z, bb.w);
            float am[4] = { a.x, a.y, a.z, a.w };
#pragma unroll
            for (int i = 0; i < 4; i++) {
                u64 ap = pack2(am[i], am[i]);
                ffma2(s2[i][0], ap, bp0);
                ffma2(s2[i][1], ap, bp1);
            }
        }

        // online softmax over this 64-wide slab
        float4 mk = *(const float4*)&maskg[b * LSEQ + k0 + tx * 4];
        float p[4][4];
#pragma unroll
        for (int i = 0; i < 4; i++) {
            float2 f0 = unpack2(s2[i][0]);
            float2 f1 = unpack2(s2[i][1]);
            float sv0 = f0.x * 0.25f + mk.x;
            float sv1 = f0.y * 0.25f + mk.y;
            float sv2 = f1.x * 0.25f + mk.z;
            float sv3 = f1.y * 0.25f + mk.w;
            float rm = fmaxf(fmaxf(sv0, sv1), fmaxf(sv2, sv3));
#pragma unroll
            for (int o = 8; o >= 1; o >>= 1)
                rm = fmaxf(rm, __shfl_xor_sync(0xffffffffu, rm, o));
            float mnew = fmaxf(mrow[i], rm);
            float corr = __expf(mrow[i] - mnew);
            mrow[i] = mnew;
            p[i][0] = __expf(sv0 - mnew);
            p[i][1] = __expf(sv1 - mnew);
            p[i][2] = __expf(sv2 - mnew);
            p[i][3] = __expf(sv3 - mnew);
            float rs = p[i][0] + p[i][1] + p[i][2] + p[i][3];
#pragma unroll
            for (int o = 8; o >= 1; o >>= 1)
                rs += __shfl_xor_sync(0xffffffffu, rs, o);
            lrow[i] = lrow[i] * corr + rs;
            u64 cp = pack2(corr, corr);
            fmul2(acc[i][0], cp);
            fmul2(acc[i][1], cp);
        }

        __syncthreads();   // all GEMM1 reads of VPs (V tile) complete
        // store P into VPs, i-major: Ps[i][j]
#pragma unroll
        for (int i = 0; i < 4; i++) {
            float4 pv = make_float4(p[i][0], p[i][1], p[i][2], p[i][3]);
            *(float4*)&VPs[(ty * 4 + i) * 64 + tx * 4] = pv;
        }
        __syncthreads();

        // GEMM2: acc[i][d] += sum_j Ps[i][j] * Ks[j][d]
#pragma unroll 8
        for (int j = 0; j < 64; j++) {
            float4 bb = *(const float4*)&Ks[j * 64 + tx * 4];
            u64 bp0 = pack2(bb.x, bb.y), bp1 = pack2(bb.z, bb.w);
#pragma unroll
            for (int i = 0; i < 4; i++) {
                float av = VPs[(ty * 4 + i) * 64 + j];
                u64 ap = pack2(av, av);
                ffma2(acc[i][0], ap, bp0);
                ffma2(acc[i][1], ap, bp1);
            }
        }
    }

    // epilogue: O = acc / l
#pragma unroll
    for (int i = 0; i < 4; i++) {
        float inv = 1.0f / lrow[i];
        float2 f0 = unpack2(acc[i][0]);
        float2 f1 = unpack2(acc[i][1]);
        float4 o = make_float4(f0.x * inv, f0.y * inv, f1.x * inv, f1.y * inv);
        size_t off = (size_t)(b * LSEQ + q0 + ty * 4 + i) * NDIM + h * HEADD + tx * 4;
        *(float4*)&Og[off] = o;
    }
}

// ---------------------------------------------------------------------------
// Row LayerNorm: out = (x - mu) * rsqrt(var + eps) * gamma + beta
// one block (256 threads) per row of 1024
// ---------------------------------------------------------------------------
__global__ __launch_bounds__(256)
void ln_kernel(const float* __restrict__ X, const float* __restrict__ gamma,
               const float* __restrict__ beta, float* __restrict__ out)
{
    __shared__ float red[8];
    const int row = blockIdx.x;
    const int tid = threadIdx.x;

    float4 x = *(const float4*)&X[(size_t)row * NDIM + tid * 4];
    float s = x.x + x.y + x.z + x.w;
#pragma unroll
    for (int o = 16; o >= 1; o >>= 1) s += __shfl_xor_sync(0xffffffffu, s, o);
    if ((tid & 31) == 0) red[tid >> 5] = s;
    __syncthreads();
    float tot = 0.f;
#pragma unroll
    for (int w = 0; w < 8; w++) tot += red[w];
    float mu = tot * (1.0f / 1024.0f);

    float d0 = x.x - mu, d1 = x.y - mu, d2 = x.z - mu, d3 = x.w - mu;
    float ss = d0 * d0 + d1 * d1 + d2 * d2 + d3 * d3;
#pragma unroll
    for (int o = 16; o >= 1; o >>= 1) ss += __shfl_xor_sync(0xffffffffu, ss, o);
    __syncthreads();
    if ((tid & 31) == 0) red[tid >> 5] = ss;
    __syncthreads();
    float tot2 = 0.f;
#pragma unroll
    for (int w = 0; w < 8; w++) tot2 += red[w];
    float var = tot2 * (1.0f / 1024.0f);
    float r = rsqrtf(var + 1e-12f);

    float4 g  = *(const float4*)&gamma[tid * 4];
    float4 bt = *(const float4*)&beta[tid * 4];
    float4 o4;
    o4.x = d0 * r * g.x + bt.x;
    o4.y = d1 * r * g.y + bt.y;
    o4.z = d2 * r * g.z + bt.z;
    o4.w = d3 * r * g.w + bt.w;
    *(float4*)&out[(size_t)row * NDIM + tid * 4] = o4;
}

// ---------------------------------------------------------------------------
extern "C" void kernel_launch(void* const* d_in, const int* in_sizes, int n_in,
                              void* d_out, int out_size)
{
    const float* E    = (const float*)d_in[0];
    const float* mask = (const float*)d_in[1];
    const float* Wq   = (const float*)d_in[2];
    const float* bq   = (const float*)d_in[3];
    const float* Wk   = (const float*)d_in[4];
    const float* bk   = (const float*)d_in[5];
    const float* Wv   = (const float*)d_in[6];
    const float* bv   = (const float*)d_in[7];
    const float* Wo   = (const float*)d_in[8];
    const float* bo   = (const float*)d_in[9];
    const float* lng  = (const float*)d_in[10];
    const float* lnb  = (const float*)d_in[11];
    float* out = (float*)d_out;

    float *qp, *kp, *vp, *ap, *op;
    cudaGetSymbolAddress((void**)&qp, g_q);
    cudaGetSymbolAddress((void**)&kp, g_k);
    cudaGetSymbolAddress((void**)&vp, g_v);
    cudaGetSymbolAddress((void**)&ap, g_att);
    cudaGetSymbolAddress((void**)&op, g_o);

    // 1) fused QKV projections
    gemm_bias_kernel<<<dim3(8, 32, 3), 256>>>(E, Wq, Wk, Wv, bq, bk, bv,
                                              qp, kp, vp, nullptr);
    // 2) flash attention (S = Q@V^T/4 + mask, A = P@K)
    flash_attn_kernel<<<dim3(32, 32), 256>>>(qp, kp, vp, mask, ap);
    // 3) output projection + bias + residual
    gemm_bias_kernel<<<dim3(8, 32, 1), 256>>>(ap, Wo, Wo, Wo, bo, bo, bo,
                                              op, op, op, E);
    // 4) layernorm
    ln_kernel<<<4096, 256>>>(op, lng, lnb, out);
}

// round 11
// speedup vs baseline: 1.2492x; 1.2492x over previous
#include <cuda_runtime.h>
#include <cuda_bf16.h>
#include <cstdint>

// ===========================================================================
// BERT attention block. R7: projection GEMMs on mma.sync bf16 (HMMA) with
// 3-term fp32 emulation (hi/lo bf16 split). Flash attention fp32 FFMA2.
//   B=2, L=2048, H=1024, NH=16, D=64
// NOTE: harness ptxas targets base sm_103 (no 'a' features) -> no tcgen05.
// ===========================================================================

typedef unsigned long long u64;

__device__ __forceinline__ u64 pack2(float lo, float hi) {
    u64 r; asm("mov.b64 %0, {%1, %2};" : "=l"(r) : "f"(lo), "f"(hi)); return r;
}
__device__ __forceinline__ float2 unpack2(u64 v) {
    float2 f; asm("mov.b64 {%0, %1}, %2;" : "=f"(f.x), "=f"(f.y) : "l"(v)); return f;
}
__device__ __forceinline__ void ffma2(u64& d, u64 a, u64 b) {
    asm("fma.rn.f32x2 %0, %1, %2, %0;" : "+l"(d) : "l"(a), "l"(b));
}
__device__ __forceinline__ void fmul2(u64& d, u64 s) {
    asm("mul.rn.f32x2 %0, %0, %1;" : "+l"(d) : "l"(s));
}
__device__ __forceinline__ uint32_t smem_to_u32(const void* p) {
    uint32_t a;
    asm("{ .reg .u64 t; cvta.to.shared.u64 t, %1; cvt.u32.u64 %0, t; }"
        : "=r"(a) : "l"(p));
    return a;
}

// ---- mma.sync building blocks (sm_80+, valid on base sm_103) --------------
__device__ __forceinline__ void ldmx4(uint32_t* r, uint32_t addr) {
    asm volatile("ldmatrix.sync.aligned.m8n8.x4.shared.b16 {%0,%1,%2,%3}, [%4];"
                 : "=r"(r[0]), "=r"(r[1]), "=r"(r[2]), "=r"(r[3]) : "r"(addr));
}
__device__ __forceinline__ void ldmx2(uint32_t* r, uint32_t addr) {
    asm volatile("ldmatrix.sync.aligned.m8n8.x2.shared.b16 {%0,%1}, [%2];"
                 : "=r"(r[0]), "=r"(r[1]) : "r"(addr));
}
__device__ __forceinline__ void mma_bf16(float* c, const uint32_t* a, const uint32_t* b) {
    asm volatile("mma.sync.aligned.m16n8k16.row.col.f32.bf16.bf16.f32 "
                 "{%0,%1,%2,%3}, {%4,%5,%6,%7}, {%8,%9}, {%0,%1,%2,%3};"
                 : "+f"(c[0]), "+f"(c[1]), "+f"(c[2]), "+f"(c[3])
                 : "r"(a[0]), "r"(a[1]), "r"(a[2]), "r"(a[3]), "r"(b[0]), "r"(b[1]));
}
#define CP_ASYNC16(dst, src) \
    asm volatile("cp.async.cg.shared.global [%0], [%1], 16;" :: "r"(dst), "l"(src))
#define CP_COMMIT() asm volatile("cp.async.commit_group;" ::: "memory")
#define CP_WAIT1()  asm volatile("cp.async.wait_group 1;" ::: "memory")
#define CP_WAIT0()  asm volatile("cp.async.wait_group 0;" ::: "memory")

#define MDIM 4096
#define NDIM 1024
#define KDIM 1024
#define LSEQ 2048
#define HEADD 64

// GEMM smem geometry: 4 tiles (Ah, Al, Bh, Bl) of 128 rows x 32 bf16,
// row stride 56 elems = 112B (7 x 16B: ldmatrix conflict-free), 2 stages.
#define TROWB   112
#define TILEB   (128 * TROWB)       // 14336
#define STAGEB  (4 * TILEB)         // 57344
#define GEMM_SMEM (2 * STAGEB)      // 114688

// ---------------- scratch (__device__ globals; no allocation) --------------
__device__ float g_q[MDIM * NDIM];
__device__ float g_k[MDIM * NDIM];
__device__ float g_v[MDIM * NDIM];
__device__ float g_att[MDIM * NDIM];
__device__ float g_o[MDIM * NDIM];
__device__ __nv_bfloat16 g_ehi[MDIM * NDIM];
__device__ __nv_bfloat16 g_elo[MDIM * NDIM];
__device__ __nv_bfloat16 g_athi[MDIM * NDIM];
__device__ __nv_bfloat16 g_atlo[MDIM * NDIM];
__device__ __nv_bfloat16 g_wthi[4 * NDIM * KDIM];
__device__ __nv_bfloat16 g_wtlo[4 * NDIM * KDIM];

// ---------------------------------------------------------------------------
// split fp32 -> (hi, lo) bf16, same layout
// ---------------------------------------------------------------------------
__global__ __launch_bounds__(256)
void split_bf16_kernel(const float* __restrict__ x, __nv_bfloat16* __restrict__ hi,
                       __nv_bfloat16* __restrict__ lo, int n4)
{
    int i = blockIdx.x * blockDim.x + threadIdx.x;
    if (i >= n4) return;
    float4 v = ((const float4*)x)[i];
    __nv_bfloat16 h0 = __float2bfloat16_rn(v.x);
    __nv_bfloat16 h1 = __float2bfloat16_rn(v.y);
    __nv_bfloat16 h2 = __float2bfloat16_rn(v.z);
    __nv_bfloat16 h3 = __float2bfloat16_rn(v.w);
    __nv_bfloat16 l0 = __float2bfloat16_rn(v.x - __bfloat162float(h0));
    __nv_bfloat16 l1 = __float2bfloat16_rn(v.y - __bfloat162float(h1));
    __nv_bfloat16 l2 = __float2bfloat16_rn(v.z - __bfloat162float(h2));
    __nv_bfloat16 l3 = __float2bfloat16_rn(v.w - __bfloat162float(h3));
    ((__nv_bfloat162*)hi)[i * 2 + 0] = __nv_bfloat162(h0, h1);
    ((__nv_bfloat162*)hi)[i * 2 + 1] = __nv_bfloat162(h2, h3);
    ((__nv_bfloat162*)lo)[i * 2 + 0] = __nv_bfloat162(l0, l1);
    ((__nv_bfloat162*)lo)[i * 2 + 1] = __nv_bfloat162(l2, l3);
}

// ---------------------------------------------------------------------------
// transpose + split the 4 weight matrices: Wt[z][n][k] = W_z[k][n] as hi/lo
// ---------------------------------------------------------------------------
__global__ __launch_bounds__(256)
void wtrans_kernel(const float* __restrict__ w0, const float* __restrict__ w1,
                   const float* __restrict__ w2, const float* __restrict__ w3,
                   __nv_bfloat16* __restrict__ hi, __nv_bfloat16* __restrict__ lo)
{
    __shared__ float t[32][33];
    const float* W = (blockIdx.z == 0) ? w0 : (blockIdx.z == 1) ? w1
                    : (blockIdx.z == 2) ? w2 : w3;
    int tx = threadIdx.x & 31, ty = threadIdx.x >> 5;
    int k0 = blockIdx.y * 32, n0 = blockIdx.x * 32;
#pragma unroll
    for (int i = 0; i < 4; i++)
        t[ty + i * 8][tx] = W[(size_t)(k0 + ty + i * 8) * NDIM + n0 + tx];
    __syncthreads();
    size_t base = (size_t)blockIdx.z * NDIM * KDIM;
#pragma unroll
    for (int i = 0; i < 4; i++) {
        float v = t[tx][ty + i * 8];
        __nv_bfloat16 h = __float2bfloat16_rn(v);
        __nv_bfloat16 l = __float2bfloat16_rn(v - __bfloat162float(h));
        size_t idx = base + (size_t)(n0 + ty + i * 8) * KDIM + k0 + tx;
        hi[idx] = h; lo[idx] = l;
    }
}

// ---------------------------------------------------------------------------
// HMMA GEMM: O = A[M,K] @ Wt[z][N,K]^T + bias (+resid), fp32 via bf16x3.
// CTA tile 128x128, 8 warps (warp tile 64x32), K-step 32, cp.async 2-stage.
// ---------------------------------------------------------------------------
__device__ __forceinline__ void issue_stage(uint32_t sbase,
    const __nv_bfloat16* __restrict__ Ah, const __nv_bfloat16* __restrict__ Al,
    const __nv_bfloat16* __restrict__ Bh, const __nv_bfloat16* __restrict__ Bl,
    int m0, int n0, int k0, int tid)
{
#pragma unroll
    for (int t = 0; t < 4; t++) {
        const __nv_bfloat16* g = (t == 0) ? Ah : (t == 1) ? Al : (t == 2) ? Bh : Bl;
        const int row0 = (t < 2) ? m0 : n0;
        const uint32_t st = sbase + t * TILEB;
#pragma unroll
        for (int u = 0; u < 2; u++) {
            int idx = tid + u * 256;
            int r = idx >> 2, c = idx & 3;
            const void* src = g + (size_t)(row0 + r) * KDIM + k0 + c * 8;
            CP_ASYNC16(st + r * TROWB + c * 16, src);
        }
    }
    CP_COMMIT();
}

__global__ __launch_bounds__(256, 1)
void gemm_mma_kernel(const __nv_bfloat16* __restrict__ Ah, const __nv_bfloat16* __restrict__ Al,
                     const __nv_bfloat16* __restrict__ Wh, const __nv_bfloat16* __restrict__ Wl,
                     int wbase,
                     const float* __restrict__ b0, const float* __restrict__ b1,
                     const float* __restrict__ b2,
                     float* __restrict__ O0, float* __restrict__ O1, float* __restrict__ O2,
                     const float* __restrict__ resid)
{
    extern __shared__ char smem[];
    const uint32_t sb = smem_to_u32(smem);
    const int tid = threadIdx.x, lane = tid & 31, wid = tid >> 5;
    const int wm = wid >> 2, wn = wid & 3;               // 2 x 4 warp grid
    const int m0 = blockIdx.y * 128, n0 = blockIdx.x * 128, z = blockIdx.z;
    const float* bias = (z == 0) ? b0 : (z == 1) ? b1 : b2;
    float* O = (z == 0) ? O0 : (z == 1) ? O1 : O2;
    const __nv_bfloat16* WhS = Wh + (size_t)(wbase + z) * NDIM * KDIM;
    const __nv_bfloat16* WlS = Wl + (size_t)(wbase + z) * NDIM * KDIM;

    float acc[4][4][4];
#pragma unroll
    for (int i = 0; i < 4; i++)
#pragma unroll
        for (int j = 0; j < 4; j++)
#pragma unroll
            for (int q = 0; q < 4; q++) acc[i][j][q] = 0.f;

    // per-thread ldmatrix address offsets (within a tile)
    const uint32_t aoff = (uint32_t)((wm * 64 + (lane & 15)) * TROWB + ((lane >> 4) << 3) * 2);
    const uint32_t boff = (uint32_t)((wn * 32 + (lane & 7)) * TROWB + (((lane >> 3) & 1) << 3) * 2);

    issue_stage(sb, Ah, Al, WhS, WlS, m0, n0, 0, tid);

    const int NIT = KDIM / 32;   // 32
    for (int it = 0; it < NIT; it++) {
        if (it + 1 < NIT) {
            issue_stage(sb + ((it + 1) & 1) * STAGEB, Ah, Al, WhS, WlS,
                        m0, n0, (it + 1) * 32, tid);
            CP_WAIT1();
        } else {
            CP_WAIT0();
        }
        __syncthreads();

        const uint32_t sA = sb + (it & 1) * STAGEB;
        const uint32_t sAl_ = sA + TILEB;
        const uint32_t sBh_ = sA + 2 * TILEB;
        const uint32_t sBl_ = sA + 3 * TILEB;

#pragma unroll
        for (int kk = 0; kk < 2; kk++) {
            const uint32_t ko = kk * 32;   // 16 elems * 2B
            uint32_t ah[4][4], al[4][4], bh[4][2], bl[4][2];
#pragma unroll
            for (int i = 0; i < 4; i++) ldmx4(ah[i], sA   + aoff + i * (16 * TROWB) + ko);
#pragma unroll
            for (int i = 0; i < 4; i++) ldmx4(al[i], sAl_ + aoff + i * (16 * TROWB) + ko);
#pragma unroll
            for (int j = 0; j < 4; j++) ldmx2(bh[j], sBh_ + boff + j * (8 * TROWB) + ko);
#pragma unroll
            for (int j = 0; j < 4; j++) ldmx2(bl[j], sBl_ + boff + j * (8 * TROWB) + ko);
#pragma unroll
            for (int i = 0; i < 4; i++)
#pragma unroll
                for (int j = 0; j < 4; j++) {
                    mma_bf16(acc[i][j], ah[i], bh[j]);
                    mma_bf16(acc[i][j], ah[i], bl[j]);
                    mma_bf16(acc[i][j], al[i], bh[j]);
                }
        }
        __syncthreads();
    }

    // epilogue: frag (i,j) -> rows m0+wm*64+i*16+{lane/4, +8}, cols n0+wn*32+j*8+(lane%3)*2
    const int r0 = lane >> 2, c0 = (lane & 3) * 2;
#pragma unroll
    for (int i = 0; i < 4; i++) {
#pragma unroll
        for (int half = 0; half < 2; half++) {
            const int row = m0 + wm * 64 + i * 16 + r0 + half * 8;
            float* op = O + (size_t)row * NDIM;
            const float* rp = resid ? resid + (size_t)row * NDIM : nullptr;
#pragma unroll
            for (int j = 0; j < 4; j++) {
                const int col = n0 + wn * 32 + j * 8 + c0;
                float vx = acc[i][j][half * 2 + 0] + bias[col];
                float vy = acc[i][j][half * 2 + 1] + bias[col + 1];
                if (rp) { vx += rp[col]; vy += rp[col + 1]; }
                *(float2*)&op[col] = make_float2(vx, vy);
            }
        }
    }
}

// ---------------------------------------------------------------------------
// Flash attention per (b, head, 64-query tile). fp32 FFMA2 (unchanged).
// ---------------------------------------------------------------------------
__global__ __launch_bounds__(256, 2)
void flash_attn_kernel(const float* __restrict__ Qg, const float* __restrict__ Kg,
                       const float* __restrict__ Vg, const float* __restrict__ maskg,
                       float* __restrict__ Og)
{
    __shared__ float Qs[64 * 64];
    __shared__ float VPs[64 * 64];
    __shared__ float Ks[64 * 64];

    const int tid = threadIdx.x;
    const int tx  = tid & 15;
    const int ty  = tid >> 4;
    const int bh  = blockIdx.y;
    const int b   = bh >> 4;
    const int h   = bh & 15;
    const int q0  = blockIdx.x * 64;
    const int li  = tid >> 2;
    const int ld0 = (tid & 3) * 16;

    {
        const float* qp = Qg + (size_t)(b * LSEQ + q0 + li) * NDIM + h * HEADD + ld0;
#pragma unroll
        for (int u = 0; u < 4; u++) {
            float4 v = *(const float4*)(qp + u * 4);
            int d = ld0 + u * 4;
            Qs[(d + 0) * 64 + li] = v.x;
            Qs[(d + 1) * 64 + li] = v.y;
            Qs[(d + 2) * 64 + li] = v.z;
            Qs[(d + 3) * 64 + li] = v.w;
        }
    }

    float mrow[4], lrow[4];
    u64 acc[4][2];
#pragma unroll
    for (int i = 0; i < 4; i++) {
        mrow[i] = -1e30f; lrow[i] = 0.f; acc[i][0] = 0ull; acc[i][1] = 0ull;
    }

    for (int kt = 0; kt < 32; kt++) {
        const int k0 = kt * 64;
        const float* kp = Kg + (size_t)(b * LSEQ + k0 + li) * NDIM + h * HEADD + ld0;
        const float* vp = Vg + (size_t)(b * LSEQ + k0 + li) * NDIM + h * HEADD + ld0;

        __syncthreads();
#pragma unroll
        for (int u = 0; u < 4; u++) {
            float4 v = *(const float4*)(vp + u * 4);
            int d = ld0 + u * 4;
            VPs[(d + 0) * 64 + li] = v.x;
            VPs[(d + 1) * 64 + li] = v.y;
            VPs[(d + 2) * 64 + li] = v.z;
            VPs[(d + 3) * 64 + li] = v.w;
            float4 kv = *(const float4*)(kp + u * 4);
            *(float4*)&Ks[li * 64 + ld0 + u * 4] = kv;
        }
        __syncthreads();

        u64 s2[4][2];
#pragma unroll
        for (int i = 0; i < 4; i++) { s2[i][0] = 0ull; s2[i][1] = 0ull; }
#pragma unroll 8
        for (int d = 0; d < 64; d++) {
            float4 a  = *(const float4*)&Qs[d * 64 + ty * 4];
            float4 bb = *(const float4*)&VPs[d * 64 + tx * 4];
            u64 bp0 = pack2(bb.x, bb.y), bp1 = pack2(bb.z, bb.w);
            float am[4] = { a.x, a.y, a.z, a.w };
#pragma unroll
            for (int i = 0; i < 4; i++) {
                u64 ap = pack2(am[i], am[i]);
                ffma2(s2[i][0], ap, bp0);
                ffma2(s2[i][1], ap, bp1);
            }
        }

        float4 mk = *(const float4*)&maskg[b * LSEQ + k0 + tx * 4];
        float p[4][4];
#pragma unroll
        for (int i = 0; i < 4; i++) {
            float2 f0 = unpack2(s2[i][0]);
            float2 f1 = unpack2(s2[i][1]);
            float sv0 = f0.x * 0.25f + mk.x;
            float sv1 = f0.y * 0.25f + mk.y;
            float sv2 = f1.x * 0.25f + mk.z;
            float sv3 = f1.y * 0.25f + mk.w;
            float rm = fmaxf(fmaxf(sv0, sv1), fmaxf(sv2, sv3));
#pragma unroll
            for (int o = 8; o >= 1; o >>= 1)
                rm = fmaxf(rm, __shfl_xor_sync(0xffffffffu, rm, o));
            float mnew = fmaxf(mrow[i], rm);
            float corr = __expf(mrow[i] - mnew);
            mrow[i] = mnew;
            p[i][0] = __expf(sv0 - mnew);
            p[i][1] = __expf(sv1 - mnew);
            p[i][2] = __expf(sv2 - mnew);
            p[i][3] = __expf(sv3 - mnew);
            float rs = p[i][0] + p[i][1] + p[i][2] + p[i][3];
#pragma unroll
            for (int o = 8; o >= 1; o >>= 1)
                rs += __shfl_xor_sync(0xffffffffu, rs, o);
            lrow[i] = lrow[i] * corr + rs;
            u64 cp = pack2(corr, corr);
            fmul2(acc[i][0], cp);
            fmul2(acc[i][1], cp);
        }

        __syncthreads();
#pragma unroll
        for (int i = 0; i < 4; i++) {
            float4 pv = make_float4(p[i][0], p[i][1], p[i][2], p[i][3]);
            *(float4*)&VPs[(ty * 4 + i) * 64 + tx * 4] = pv;
        }
        __syncthreads();

#pragma unroll 8
        for (int j = 0; j < 64; j++) {
            float4 bb = *(const float4*)&Ks[j * 64 + tx * 4];
            u64 bp0 = pack2(bb.x, bb.y), bp1 = pack2(bb.z, bb.w);
#pragma unroll
            for (int i = 0; i < 4; i++) {
                float av = VPs[(ty * 4 + i) * 64 + j];
                u64 ap = pack2(av, av);
                ffma2(acc[i][0], ap, bp0);
                ffma2(acc[i][1], ap, bp1);
            }
        }
    }

#pragma unroll
    for (int i = 0; i < 4; i++) {
        float inv = 1.0f / lrow[i];
        float2 f0 = unpack2(acc[i][0]);
        float2 f1 = unpack2(acc[i][1]);
        float4 o = make_float4(f0.x * inv, f0.y * inv, f1.x * inv, f1.y * inv);
        size_t off = (size_t)(b * LSEQ + q0 + ty * 4 + i) * NDIM + h * HEADD + tx * 4;
        *(float4*)&Og[off] = o;
    }
}

// ---------------------------------------------------------------------------
// Row LayerNorm
// ---------------------------------------------------------------------------
__global__ __launch_bounds__(256)
void ln_kernel(const float* __restrict__ X, const float* __restrict__ gamma,
               const float* __restrict__ beta, float* __restrict__ out)
{
    __shared__ float red[8];
    const int row = blockIdx.x;
    const int tid = threadIdx.x;

    float4 x = *(const float4*)&X[(size_t)row * NDIM + tid * 4];
    float s = x.x + x.y + x.z + x.w;
#pragma unroll
    for (int o = 16; o >= 1; o >>= 1) s += __shfl_xor_sync(0xffffffffu, s, o);
    if ((tid & 31) == 0) red[tid >> 5] = s;
    __syncthreads();
    float tot = 0.f;
#pragma unroll
    for (int w = 0; w < 8; w++) tot += red[w];
    float mu = tot * (1.0f / 1024.0f);

    float d0 = x.x - mu, d1 = x.y - mu, d2 = x.z - mu, d3 = x.w - mu;
    float ss = d0 * d0 + d1 * d1 + d2 * d2 + d3 * d3;
#pragma unroll
    for (int o = 16; o >= 1; o >>= 1) ss += __shfl_xor_sync(0xffffffffu, ss, o);
    __syncthreads();
    if ((tid & 31) == 0) red[tid >> 5] = ss;
    __syncthreads();
    float tot2 = 0.f;
#pragma unroll
    for (int w = 0; w < 8; w++) tot2 += red[w];
    float var = tot2 * (1.0f / 1024.0f);
    float r = rsqrtf(var + 1e-12f);

    float4 g  = *(const float4*)&gamma[tid * 4];
    float4 bt = *(const float4*)&beta[tid * 4];
    float4 o4;
    o4.x = d0 * r * g.x + bt.x;
    o4.y = d1 * r * g.y + bt.y;
    o4.z = d2 * r * g.z + bt.z;
    o4.w = d3 * r * g.w + bt.w;
    *(float4*)&out[(size_t)row * NDIM + tid * 4] = o4;
}

// ---------------------------------------------------------------------------
extern "C" void kernel_launch(void* const* d_in, const int* in_sizes, int n_in,
                              void* d_out, int out_size)
{
    const float* E    = (const float*)d_in[0];
    const float* mask = (const float*)d_in[1];
    const float* Wq   = (const float*)d_in[2];
    const float* bq   = (const float*)d_in[3];
    const float* Wk   = (const float*)d_in[4];
    const float* bk   = (const float*)d_in[5];
    const float* Wv   = (const float*)d_in[6];
    const float* bv   = (const float*)d_in[7];
    const float* Wo   = (const float*)d_in[8];
    const float* bo   = (const float*)d_in[9];
    const float* lng  = (const float*)d_in[10];
    const float* lnb  = (const float*)d_in[11];
    float* out = (float*)d_out;

    float *qp, *kp, *vp, *ap, *op;
    __nv_bfloat16 *ehi, *elo, *athi, *atlo, *wth, *wtl;
    cudaGetSymbolAddress((void**)&qp, g_q);
    cudaGetSymbolAddress((void**)&kp, g_k);
    cudaGetSymbolAddress((void**)&vp, g_v);
    cudaGetSymbolAddress((void**)&ap, g_att);
    cudaGetSymbolAddress((void**)&op, g_o);
    cudaGetSymbolAddress((void**)&ehi, g_ehi);
    cudaGetSymbolAddress((void**)&elo, g_elo);
    cudaGetSymbolAddress((void**)&athi, g_athi);
    cudaGetSymbolAddress((void**)&atlo, g_atlo);
    cudaGetSymbolAddress((void**)&wth, g_wthi);
    cudaGetSymbolAddress((void**)&wtl, g_wtlo);

    cudaFuncSetAttribute(gemm_mma_kernel,
                         cudaFuncAttributeMaxDynamicSharedMemorySize, GEMM_SMEM);

    // 0) precision splits: E -> bf16 hi/lo; W -> transposed bf16 hi/lo
    split_bf16_kernel<<<4096, 256>>>(E, ehi, elo, MDIM * NDIM / 4);
    wtrans_kernel<<<dim3(32, 32, 4), 256>>>(Wq, Wk, Wv, Wo, wth, wtl);

    // 1) fused QKV projections (HMMA bf16x3)
    gemm_mma_kernel<<<dim3(8, 32, 3), 256, GEMM_SMEM>>>(
        ehi, elo, wth, wtl, 0, bq, bk, bv, qp, kp, vp, nullptr);

    // 2) flash attention (S = Q@V^T/4 + mask, A = P@K)
    flash_attn_kernel<<<dim3(32, 32), 256>>>(qp, kp, vp, mask, ap);

    // 3) output projection + bias + residual (HMMA bf16x3)
    split_bf16_kernel<<<4096, 256>>>(ap, athi, atlo, MDIM * NDIM / 4);
    gemm_mma_kernel<<<dim3(8, 32, 1), 256, GEMM_SMEM>>>(
        athi, atlo, wth, wtl, 3, bo, bo, bo, op, op, op, E);

    // 4) layernorm
    ln_kernel<<<4096, 256>>>(op, lng, lnb, out);
}

// round 14
// speedup vs baseline: 2.3101x; 1.8492x over previous
#include <cuda_runtime.h>
#include <cuda_bf16.h>
#include <cstdint>

// ===========================================================================
// BERT attention block. R12: everything tensor-core (mma.sync bf16 x3-term
// fp32 emulation). Flash attention on HMMA with hybrid MUFU/FFMA2-poly exp.
//   B=2, L=2048, H=1024, NH=16, D=64
// ===========================================================================

typedef unsigned long long u64;

__device__ __forceinline__ u64 pack2(float lo, float hi) {
    u64 r; asm("mov.b64 %0, {%1, %2};" : "=l"(r) : "f"(lo), "f"(hi)); return r;
}
__device__ __forceinline__ float2 unpack2(u64 v) {
    float2 f; asm("mov.b64 {%0, %1}, %2;" : "=f"(f.x), "=f"(f.y) : "l"(v)); return f;
}
__device__ __forceinline__ u64 fma2v(u64 a, u64 b, u64 c) {
    u64 d; asm("fma.rn.f32x2 %0, %1, %2, %3;" : "=l"(d) : "l"(a), "l"(b), "l"(c)); return d;
}
__device__ __forceinline__ u64 add2v(u64 a, u64 b) {
    u64 d; asm("add.rn.f32x2 %0, %1, %2;" : "=l"(d) : "l"(a), "l"(b)); return d;
}
__device__ __forceinline__ float ex2f(float x) {
    float y; asm("ex2.approx.f32 %0, %1;" : "=f"(y) : "f"(x)); return y;
}
__device__ __forceinline__ uint32_t smem_to_u32(const void* p) {
    uint32_t a;
    asm("{ .reg .u64 t; cvta.to.shared.u64 t, %1; cvt.u32.u64 %0, t; }"
        : "=r"(a) : "l"(p));
    return a;
}

// ---- mma.sync building blocks (sm_80+, valid on base sm_103) --------------
__device__ __forceinline__ void ldmx4(uint32_t* r, uint32_t addr) {
    asm volatile("ldmatrix.sync.aligned.m8n8.x4.shared.b16 {%0,%1,%2,%3}, [%4];"
                 : "=r"(r[0]), "=r"(r[1]), "=r"(r[2]), "=r"(r[3]) : "r"(addr));
}
__device__ __forceinline__ void ldmx2(uint32_t* r, uint32_t addr) {
    asm volatile("ldmatrix.sync.aligned.m8n8.x2.shared.b16 {%0,%1}, [%2];"
                 : "=r"(r[0]), "=r"(r[1]) : "r"(addr));
}
__device__ __forceinline__ void ldmx2t(uint32_t* r, uint32_t addr) {
    asm volatile("ldmatrix.sync.aligned.m8n8.x2.trans.shared.b16 {%0,%1}, [%2];"
                 : "=r"(r[0]), "=r"(r[1]) : "r"(addr));
}
__device__ __forceinline__ void mma_bf16(float* c, const uint32_t* a, const uint32_t* b) {
    asm volatile("mma.sync.aligned.m16n8k16.row.col.f32.bf16.bf16.f32 "
                 "{%0,%1,%2,%3}, {%4,%5,%6,%7}, {%8,%9}, {%0,%1,%2,%3};"
                 : "+f"(c[0]), "+f"(c[1]), "+f"(c[2]), "+f"(c[3])
                 : "r"(a[0]), "r"(a[1]), "r"(a[2]), "r"(a[3]), "r"(b[0]), "r"(b[1]));
}
#define CP_ASYNC16(dst, src) \
    asm volatile("cp.async.cg.shared.global [%0], [%1], 16;" :: "r"(dst), "l"(src))
#define CP_COMMIT() asm volatile("cp.async.commit_group;" ::: "memory")
#define CP_WAIT1()  asm volatile("cp.async.wait_group 1;" ::: "memory")
#define CP_WAIT0()  asm volatile("cp.async.wait_group 0;" ::: "memory")

#define MDIM 4096
#define NDIM 1024
#define KDIM 1024
#define LSEQ 2048
#define HEADD 64

// fast exp2: magic-round + deg-5 poly on f in [-0.5, 0.5], packed f32x2
__device__ __forceinline__ void exp2pair(float t0, float t1, float& y0, float& y1) {
    t0 = fmaxf(t0, -24.f); t1 = fmaxf(t1, -24.f);
    const float MG = 12582912.f;                  // 2^23 + 2^22
    u64 t2  = pack2(t0, t1);
    u64 fn2 = add2v(t2, pack2(MG, MG));           // round-to-nearest int in mantissa
    u64 n2  = add2v(fn2, pack2(-MG, -MG));
    u64 f2  = fma2v(n2, pack2(-1.f, -1.f), t2);   // f = t - n, in [-0.5, 0.5]
    u64 P   = pack2(1.33335581e-3f, 1.33335581e-3f);
    P = fma2v(P, f2, pack2(9.61812911e-3f, 9.61812911e-3f));
    P = fma2v(P, f2, pack2(5.55041087e-2f, 5.55041087e-2f));
    P = fma2v(P, f2, pack2(2.40226507e-1f, 2.40226507e-1f));
    P = fma2v(P, f2, pack2(6.93147182e-1f, 6.93147182e-1f));
    P = fma2v(P, f2, pack2(1.f, 1.f));
    float2 fn = unpack2(fn2), pp = unpack2(P);
    y0 = __int_as_float(__float_as_int(pp.x) + (__float_as_int(fn.x) << 23));
    y1 = __int_as_float(__float_as_int(pp.y) + (__float_as_int(fn.y) << 23));
}

__device__ __forceinline__ void packsplit(float x, float y, uint32_t& hi, uint32_t& lo) {
    __nv_bfloat16 hx = __float2bfloat16_rn(x), hy = __float2bfloat16_rn(y);
    __nv_bfloat16 lx = __float2bfloat16_rn(x - __bfloat162float(hx));
    __nv_bfloat16 ly = __float2bfloat16_rn(y - __bfloat162float(hy));
    __nv_bfloat162 h2(hx, hy), l2(lx, ly);
    hi = *(uint32_t*)&h2; lo = *(uint32_t*)&l2;
}

// GEMM smem geometry (row stride 112B: conflict-free ldmatrix)
#define TROWB   112
#define TILEB   (128 * TROWB)
#define STAGEB  (4 * TILEB)
#define GEMM_SMEM (2 * STAGEB)      // 114688

// Flash smem geometry (64-elem rows padded to 72 = 144B)
#define FROWB   144
#define QTILEB  (128 * FROWB)       // 18432
#define KVTILEB (64 * FROWB)        // 9216
#define FSTAGEB (4 * KVTILEB)       // 36864
#define FLASH_SMEM (2 * QTILEB + 2 * FSTAGEB)   // 110592

// ---------------- scratch (__device__ globals; no allocation) --------------
__device__ float g_o[MDIM * NDIM];
__device__ __nv_bfloat16 g_ehi[MDIM * NDIM];
__device__ __nv_bfloat16 g_elo[MDIM * NDIM];
__device__ __nv_bfloat16 g_qh[MDIM * NDIM];
__device__ __nv_bfloat16 g_ql[MDIM * NDIM];
__device__ __nv_bfloat16 g_kh[MDIM * NDIM];
__device__ __nv_bfloat16 g_kl[MDIM * NDIM];
__device__ __nv_bfloat16 g_vh[MDIM * NDIM];
__device__ __nv_bfloat16 g_vl[MDIM * NDIM];
__device__ __nv_bfloat16 g_athi[MDIM * NDIM];
__device__ __nv_bfloat16 g_atlo[MDIM * NDIM];
__device__ __nv_bfloat16 g_wthi[4 * NDIM * KDIM];
__device__ __nv_bfloat16 g_wtlo[4 * NDIM * KDIM];

// ---------------------------------------------------------------------------
// split fp32 -> (hi, lo) bf16
// ---------------------------------------------------------------------------
__global__ __launch_bounds__(256)
void split_bf16_kernel(const float* __restrict__ x, __nv_bfloat16* __restrict__ hi,
                       __nv_bfloat16* __restrict__ lo, int n4)
{
    int i = blockIdx.x * blockDim.x + threadIdx.x;
    if (i >= n4) return;
    float4 v = ((const float4*)x)[i];
    uint32_t h0, l0, h1, l1;
    packsplit(v.x, v.y, h0, l0);
    packsplit(v.z, v.w, h1, l1);
    ((uint32_t*)hi)[i * 2 + 0] = h0; ((uint32_t*)hi)[i * 2 + 1] = h1;
    ((uint32_t*)lo)[i * 2 + 0] = l0; ((uint32_t*)lo)[i * 2 + 1] = l1;
}

// ---------------------------------------------------------------------------
// transpose + split the 4 weight matrices: Wt[z][n][k] = W_z[k][n] as hi/lo
// ---------------------------------------------------------------------------
__global__ __launch_bounds__(256)
void wtrans_kernel(const float* __restrict__ w0, const float* __restrict__ w1,
                   const float* __restrict__ w2, const float* __restrict__ w3,
                   __nv_bfloat16* __restrict__ hi, __nv_bfloat16* __restrict__ lo)
{
    __shared__ float t[32][33];
    const float* W = (blockIdx.z == 0) ? w0 : (blockIdx.z == 1) ? w1
                    : (blockIdx.z == 2) ? w2 : w3;
    int tx = threadIdx.x & 31, ty = threadIdx.x >> 5;
    int k0 = blockIdx.y * 32, n0 = blockIdx.x * 32;
#pragma unroll
    for (int i = 0; i < 4; i++)
        t[ty + i * 8][tx] = W[(size_t)(k0 + ty + i * 8) * NDIM + n0 + tx];
    __syncthreads();
    size_t base = (size_t)blockIdx.z * NDIM * KDIM;
#pragma unroll
    for (int i = 0; i < 4; i++) {
        float v = t[tx][ty + i * 8];
        __nv_bfloat16 h = __float2bfloat16_rn(v);
        __nv_bfloat16 l = __float2bfloat16_rn(v - __bfloat162float(h));
        size_t idx = base + (size_t)(n0 + ty + i * 8) * KDIM + k0 + tx;
        hi[idx] = h; lo[idx] = l;
    }
}

// ---------------------------------------------------------------------------
// HMMA GEMM: O = A[M,K] @ Wt[z][N,K]^T + bias (+resid or bf16 hi/lo out).
// CTA tile 128x128, 8 warps (warp tile 64x32), K-step 32, cp.async 2-stage.
// ---------------------------------------------------------------------------
__device__ __forceinline__ void issue_stage(uint32_t sbase,
    const __nv_bfloat16* __restrict__ Ah, const __nv_bfloat16* __restrict__ Al,
    const __nv_bfloat16* __restrict__ Bh, const __nv_bfloat16* __restrict__ Bl,
    int m0, int n0, int k0, int tid)
{
#pragma unroll
    for (int t = 0; t < 4; t++) {
        const __nv_bfloat16* g = (t == 0) ? Ah : (t == 1) ? Al : (t == 2) ? Bh : Bl;
        const int row0 = (t < 2) ? m0 : n0;
        const uint32_t st = sbase + t * TILEB;
#pragma unroll
        for (int u = 0; u < 2; u++) {
            int idx = tid + u * 256;
            int r = idx >> 2, c = idx & 3;
            const void* src = g + (size_t)(row0 + r) * KDIM + k0 + c * 8;
            CP_ASYNC16(st + r * TROWB + c * 16, src);
        }
    }
    CP_COMMIT();
}

__global__ __launch_bounds__(256, 1)
void gemm_mma_kernel(const __nv_bfloat16* __restrict__ Ah, const __nv_bfloat16* __restrict__ Al,
                     const __nv_bfloat16* __restrict__ Wh, const __nv_bfloat16* __restrict__ Wl,
                     int wbase,
                     const float* __restrict__ b0, const float* __restrict__ b1,
                     const float* __restrict__ b2,
                     float* __restrict__ O0, float* __restrict__ O1, float* __restrict__ O2,
                     const float* __restrict__ resid,
                     __nv_bfloat16* __restrict__ H0, __nv_bfloat16* __restrict__ H1,
                     __nv_bfloat16* __restrict__ H2,
                     __nv_bfloat16* __restrict__ L0, __nv_bfloat16* __restrict__ L1,
                     __nv_bfloat16* __restrict__ L2, int obf)
{
    extern __shared__ char smem[];
    const uint32_t sb = smem_to_u32(smem);
    const int tid = threadIdx.x, lane = tid & 31, wid = tid >> 5;
    const int wm = wid >> 2, wn = wid & 3;
    const int m0 = blockIdx.y * 128, n0 = blockIdx.x * 128, z = blockIdx.z;
    const float* bias = (z == 0) ? b0 : (z == 1) ? b1 : b2;
    const __nv_bfloat16* WhS = Wh + (size_t)(wbase + z) * NDIM * KDIM;
    const __nv_bfloat16* WlS = Wl + (size_t)(wbase + z) * NDIM * KDIM;

    float acc[4][4][4];
#pragma unroll
    for (int i = 0; i < 4; i++)
#pragma unroll
        for (int j = 0; j < 4; j++)
#pragma unroll
            for (int q = 0; q < 4; q++) acc[i][j][q] = 0.f;

    const uint32_t aoff = (uint32_t)((wm * 64 + (lane & 15)) * TROWB + ((lane >> 4) << 3) * 2);
    const uint32_t boff = (uint32_t)((wn * 32 + (lane & 7)) * TROWB + (((lane >> 3) & 1) << 3) * 2);

    issue_stage(sb, Ah, Al, WhS, WlS, m0, n0, 0, tid);

    const int NIT = KDIM / 32;
    for (int it = 0; it < NIT; it++) {
        if (it + 1 < NIT) {
            issue_stage(sb + ((it + 1) & 1) * STAGEB, Ah, Al, WhS, WlS,
                        m0, n0, (it + 1) * 32, tid);
            CP_WAIT1();
        } else {
            CP_WAIT0();
        }
        __syncthreads();

        const uint32_t sA = sb + (it & 1) * STAGEB;
        const uint32_t sAl_ = sA + TILEB;
        const uint32_t sBh_ = sA + 2 * TILEB;
        const uint32_t sBl_ = sA + 3 * TILEB;

#pragma unroll
        for (int kk = 0; kk < 2; kk++) {
            const uint32_t ko = kk * 32;
            uint32_t ah[4][4], al[4][4], bh[4][2], bl[4][2];
#pragma unroll
            for (int i = 0; i < 4; i++) ldmx4(ah[i], sA   + aoff + i * (16 * TROWB) + ko);
#pragma unroll
            for (int i = 0; i < 4; i++) ldmx4(al[i], sAl_ + aoff + i * (16 * TROWB) + ko);
#pragma unroll
            for (int j = 0; j < 4; j++) ldmx2(bh[j], sBh_ + boff + j * (8 * TROWB) + ko);
#pragma unroll
            for (int j = 0; j < 4; j++) ldmx2(bl[j], sBl_ + boff + j * (8 * TROWB) + ko);
#pragma unroll
            for (int i = 0; i < 4; i++)
#pragma unroll
                for (int j = 0; j < 4; j++) {
                    mma_bf16(acc[i][j], ah[i], bh[j]);
                    mma_bf16(acc[i][j], ah[i], bl[j]);
                    mma_bf16(acc[i][j], al[i], bh[j]);
                }
        }
        __syncthreads();
    }

    const int r0 = lane >> 2, c0 = (lane & 3) * 2;
    if (obf) {
        __nv_bfloat16* Hp = (z == 0) ? H0 : (z == 1) ? H1 : H2;
        __nv_bfloat16* Lp = (z == 0) ? L0 : (z == 1) ? L1 : L2;
#pragma unroll
        for (int i = 0; i < 4; i++) {
#pragma unroll
            for (int half = 0; half < 2; half++) {
                const int row = m0 + wm * 64 + i * 16 + r0 + half * 8;
#pragma unroll
                for (int j = 0; j < 4; j++) {
                    const int col = n0 + wn * 32 + j * 8 + c0;
                    float vx = acc[i][j][half * 2 + 0] + bias[col];
                    float vy = acc[i][j][half * 2 + 1] + bias[col + 1];
                    uint32_t hp, lp;
                    packsplit(vx, vy, hp, lp);
                    *(uint32_t*)&Hp[(size_t)row * NDIM + col] = hp;
                    *(uint32_t*)&Lp[(size_t)row * NDIM + col] = lp;
                }
            }
        }
    } else {
        float* O = (z == 0) ? O0 : (z == 1) ? O1 : O2;
#pragma unroll
        for (int i = 0; i < 4; i++) {
#pragma unroll
            for (int half = 0; half < 2; half++) {
                const int row = m0 + wm * 64 + i * 16 + r0 + half * 8;
                float* op = O + (size_t)row * NDIM;
                const float* rp = resid ? resid + (size_t)row * NDIM : nullptr;
#pragma unroll
                for (int j = 0; j < 4; j++) {
                    const int col = n0 + wn * 32 + j * 8 + c0;
                    float vx = acc[i][j][half * 2 + 0] + bias[col];
                    float vy = acc[i][j][half * 2 + 1] + bias[col + 1];
                    if (rp) { vx += rp[col]; vy += rp[col + 1]; }
                    *(float2*)&op[col] = make_float2(vx, vy);
                }
            }
        }
    }
}

// ---------------------------------------------------------------------------
// Flash attention on HMMA. CTA = 128 q-rows x one (b,h); iterate 64-key tiles.
//   S = Q@V^T * 0.25 + mask (computed in log2 domain); online softmax with
//   hybrid exp (2 MUFU + 2 FFMA2-poly per 4 acc values); attended += P@K.
// Inputs/outputs are bf16 hi/lo splits (3-term fp32 emulation per GEMM).
// 8 warps; warp = 16 q rows x full 64-key / 64-d tile.
// ---------------------------------------------------------------------------
__device__ __forceinline__ void f_load128(uint32_t dst, const __nv_bfloat16* __restrict__ g,
                                          int b, int r0, int h, int tid) {
#pragma unroll
    for (int u = 0; u < 4; u++) {
        int idx = tid + u * 256;
        int r = idx >> 3, c = idx & 7;
        const void* src = g + (size_t)(b * LSEQ + r0 + r) * NDIM + h * HEADD + c * 8;
        CP_ASYNC16(dst + r * FROWB + c * 16, src);
    }
}
__device__ __forceinline__ void f_load64(uint32_t dst, const __nv_bfloat16* __restrict__ g,
                                         int b, int r0, int h, int tid) {
#pragma unroll
    for (int u = 0; u < 2; u++) {
        int idx = tid + u * 256;
        int r = idx >> 3, c = idx & 7;
        const void* src = g + (size_t)(b * LSEQ + r0 + r) * NDIM + h * HEADD + c * 8;
        CP_ASYNC16(dst + r * FROWB + c * 16, src);
    }
}

__global__ __launch_bounds__(256, 1)
void flash_mma_kernel(const __nv_bfloat16* __restrict__ Qh, const __nv_bfloat16* __restrict__ Ql,
                      const __nv_bfloat16* __restrict__ Kh, const __nv_bfloat16* __restrict__ Kl,
                      const __nv_bfloat16* __restrict__ Vh, const __nv_bfloat16* __restrict__ Vl,
                      const float* __restrict__ maskg,
                      __nv_bfloat16* __restrict__ Ahi, __nv_bfloat16* __restrict__ Alo)
{
    extern __shared__ char smem[];
    const uint32_t sb = smem_to_u32(smem);
    const int tid = threadIdx.x, lane = tid & 31, wid = tid >> 5;
    const int b = blockIdx.y >> 4, h = blockIdx.y & 15;
    const int q0 = blockIdx.x * 128;

    const uint32_t sQh = sb, sQl = sb + QTILEB;
    const uint32_t stg = sb + 2 * QTILEB;

    f_load128(sQh, Qh, b, q0, h, tid);
    f_load128(sQl, Ql, b, q0, h, tid);
    CP_COMMIT();
    f_load64(stg + 0 * KVTILEB, Kh, b, 0, h, tid);
    f_load64(stg + 1 * KVTILEB, Kl, b, 0, h, tid);
    f_load64(stg + 2 * KVTILEB, Vh, b, 0, h, tid);
    f_load64(stg + 3 * KVTILEB, Vl, b, 0, h, tid);
    CP_COMMIT();

    float att[8][4];
#pragma unroll
    for (int j = 0; j < 8; j++)
#pragma unroll
        for (int q = 0; q < 4; q++) att[j][q] = 0.f;
    float m0r = -1e30f, m1r = -1e30f, l0r = 0.f, l1r = 0.f;

    uint32_t aqh[4][4], aql[4][4];
    const uint32_t aoffq = (wid * 16 + (lane & 15)) * FROWB + (lane >> 4) * 16;
    const uint32_t boffv = (lane & 7) * FROWB + ((lane >> 3) & 1) * 16;
    const uint32_t bofft = (lane & 15) * FROWB;
    const float CS = 0.25f * 1.44269504089f;       // 1/4 * log2(e)
    const float LOG2E = 1.44269504089f;

    for (int kt = 0; kt < 32; kt++) {
        const int k0 = kt * 64;
        if (kt + 1 < 32) {
            const uint32_t ns = stg + ((kt + 1) & 1) * FSTAGEB;
            f_load64(ns + 0 * KVTILEB, Kh, b, k0 + 64, h, tid);
            f_load64(ns + 1 * KVTILEB, Kl, b, k0 + 64, h, tid);
            f_load64(ns + 2 * KVTILEB, Vh, b, k0 + 64, h, tid);
            f_load64(ns + 3 * KVTILEB, Vl, b, k0 + 64, h, tid);
            CP_COMMIT();
            CP_WAIT1();
        } else {
            CP_WAIT0();
        }
        __syncthreads();

        if (kt == 0) {
#pragma unroll
            for (int kk = 0; kk < 4; kk++) {
                ldmx4(aqh[kk], sQh + aoffq + kk * 32);
                ldmx4(aql[kk], sQl + aoffq + kk * 32);
            }
        }
        const uint32_t ss = stg + (kt & 1) * FSTAGEB;
        const uint32_t sKh_ = ss, sKl_ = ss + KVTILEB;
        const uint32_t sVh_ = ss + 2 * KVTILEB, sVl_ = ss + 3 * KVTILEB;

        // ---- S = Q @ V^T (3-term)
        float s[8][4];
#pragma unroll
        for (int j = 0; j < 8; j++)
#pragma unroll
            for (int q = 0; q < 4; q++) s[j][q] = 0.f;
#pragma unroll
        for (int kk = 0; kk < 4; kk++) {
#pragma unroll
            for (int j = 0; j < 8; j++) {
                uint32_t bh2[2], bl2[2];
                ldmx2(bh2, sVh_ + boffv + j * (8 * FROWB) + kk * 32);
                ldmx2(bl2, sVl_ + boffv + j * (8 * FROWB) + kk * 32);
                mma_bf16(s[j], aqh[kk], bh2);
                mma_bf16(s[j], aqh[kk], bl2);
                mma_bf16(s[j], aql[kk], bh2);
            }
        }

        // ---- online softmax in log2 domain
        const float* mp = maskg + b * LSEQ + k0 + (lane & 3) * 2;
        float rm0 = -1e30f, rm1 = -1e30f;
#pragma unroll
        for (int j = 0; j < 8; j++) {
            float mk0 = __ldg(mp + j * 8) * LOG2E;
            float mk1 = __ldg(mp + j * 8 + 1) * LOG2E;
            s[j][0] = s[j][0] * CS + mk0; s[j][1] = s[j][1] * CS + mk1;
            s[j][2] = s[j][2] * CS + mk0; s[j][3] = s[j][3] * CS + mk1;
            rm0 = fmaxf(rm0, fmaxf(s[j][0], s[j][1]));
            rm1 = fmaxf(rm1, fmaxf(s[j][2], s[j][3]));
        }
        rm0 = fmaxf(rm0, __shfl_xor_sync(0xffffffffu, rm0, 1));
        rm0 = fmaxf(rm0, __shfl_xor_sync(0xffffffffu, rm0, 2));
        rm1 = fmaxf(rm1, __shfl_xor_sync(0xffffffffu, rm1, 1));
        rm1 = fmaxf(rm1, __shfl_xor_sync(0xffffffffu, rm1, 2));
        float mn0 = fmaxf(m0r, rm0), mn1 = fmaxf(m1r, rm1);
        float cr0 = ex2f(m0r - mn0), cr1 = ex2f(m1r - mn1);
        m0r = mn0; m1r = mn1;
        float rs0 = 0.f, rs1 = 0.f;
#pragma unroll
        for (int j = 0; j < 8; j++) {
            float p0, p1;
            exp2pair(s[j][0] - mn0, s[j][1] - mn0, p0, p1);   // FFMA2 poly path
            float p2 = ex2f(s[j][2] - mn1);                   // MUFU path
            float p3 = ex2f(s[j][3] - mn1);
            s[j][0] = p0; s[j][1] = p1; s[j][2] = p2; s[j][3] = p3;
            rs0 += p0 + p1; rs1 += p2 + p3;
        }
        rs0 += __shfl_xor_sync(0xffffffffu, rs0, 1);
        rs0 += __shfl_xor_sync(0xffffffffu, rs0, 2);
        rs1 += __shfl_xor_sync(0xffffffffu, rs1, 1);
        rs1 += __shfl_xor_sync(0xffffffffu, rs1, 2);
        l0r = l0r * cr0 + rs0; l1r = l1r * cr1 + rs1;
#pragma unroll
        for (int j = 0; j < 8; j++) {
            att[j][0] *= cr0; att[j][1] *= cr0;
            att[j][2] *= cr1; att[j][3] *= cr1;
        }

        // ---- pack P into A-fragments (acc layout == A m16k16 layout)
        uint32_t pah[4][4], pal[4][4];
#pragma unroll
        for (int jp = 0; jp < 4; jp++) {
            packsplit(s[2 * jp][0],     s[2 * jp][1],     pah[jp][0], pal[jp][0]);
            packsplit(s[2 * jp][2],     s[2 * jp][3],     pah[jp][1], pal[jp][1]);
            packsplit(s[2 * jp + 1][0], s[2 * jp + 1][1], pah[jp][2], pal[jp][2]);
            packsplit(s[2 * jp + 1][2], s[2 * jp + 1][3], pah[jp][3], pal[jp][3]);
        }

        // ---- attended += P @ K (K row-major [key][d] -> B frags via ldmatrix.trans)
#pragma unroll
        for (int kp = 0; kp < 4; kp++) {
#pragma unroll
            for (int j = 0; j < 8; j++) {
                uint32_t bh2[2], bl2[2];
                ldmx2t(bh2, sKh_ + kp * (16 * FROWB) + bofft + j * 16);
                ldmx2t(bl2, sKl_ + kp * (16 * FROWB) + bofft + j * 16);
                mma_bf16(att[j], pah[kp], bh2);
                mma_bf16(att[j], pah[kp], bl2);
                mma_bf16(att[j], pal[kp], bh2);
            }
        }
        __syncthreads();   // all warps done with this stage before reuse
    }

    // ---- epilogue: attended / l -> bf16 hi/lo
    float inv0 = 1.f / l0r, inv1 = 1.f / l1r;
    const int rowA = q0 + wid * 16 + (lane >> 2), rowB = rowA + 8;
    const int colb = h * HEADD + (lane & 3) * 2;
#pragma unroll
    for (int j = 0; j < 8; j++) {
        int col = colb + j * 8;
        uint32_t hp, lp;
        packsplit(att[j][0] * inv0, att[j][1] * inv0, hp, lp);
        *(uint32_t*)&Ahi[(size_t)(b * LSEQ + rowA) * NDIM + col] = hp;
        *(uint32_t*)&Alo[(size_t)(b * LSEQ + rowA) * NDIM + col] = lp;
        packsplit(att[j][2] * inv1, att[j][3] * inv1, hp, lp);
        *(uint32_t*)&Ahi[(size_t)(b * LSEQ + rowB) * NDIM + col] = hp;
        *(uint32_t*)&Alo[(size_t)(b * LSEQ + rowB) * NDIM + col] = lp;
    }
}

// ---------------------------------------------------------------------------
// Row LayerNorm
// ---------------------------------------------------------------------------
__global__ __launch_bounds__(256)
void ln_kernel(const float* __restrict__ X, const float* __restrict__ gamma,
               const float* __restrict__ beta, float* __restrict__ out)
{
    __shared__ float red[8];
    const int row = blockIdx.x;
    const int tid = threadIdx.x;

    float4 x = *(const float4*)&X[(size_t)row * NDIM + tid * 4];
    float s = x.x + x.y + x.z + x.w;
#pragma unroll
    for (int o = 16; o >= 1; o >>= 1) s += __shfl_xor_sync(0xffffffffu, s, o);
    if ((tid & 31) == 0) red[tid >> 5] = s;
    __syncthreads();
    float tot = 0.f;
#pragma unroll
    for (int w = 0; w < 8; w++) tot += red[w];
    float mu = tot * (1.0f / 1024.0f);

    float d0 = x.x - mu, d1 = x.y - mu, d2 = x.z - mu, d3 = x.w - mu;
    float ss = d0 * d0 + d1 * d1 + d2 * d2 + d3 * d3;
#pragma unroll
    for (int o = 16; o >= 1; o >>= 1) ss += __shfl_xor_sync(0xffffffffu, ss, o);
    __syncthreads();
    if ((tid & 31) == 0) red[tid >> 5] = ss;
    __syncthreads();
    float tot2 = 0.f;
#pragma unroll
    for (int w = 0; w < 8; w++) tot2 += red[w];
    float var = tot2 * (1.0f / 1024.0f);
    float r = rsqrtf(var + 1e-12f);

    float4 g  = *(const float4*)&gamma[tid * 4];
    float4 bt = *(const float4*)&beta[tid * 4];
    float4 o4;
    o4.x = d0 * r * g.x + bt.x;
    o4.y = d1 * r * g.y + bt.y;
    o4.z = d2 * r * g.z + bt.z;
    o4.w = d3 * r * g.w + bt.w;
    *(float4*)&out[(size_t)row * NDIM + tid * 4] = o4;
}

// ---------------------------------------------------------------------------
extern "C" void kernel_launch(void* const* d_in, const int* in_sizes, int n_in,
                              void* d_out, int out_size)
{
    const float* E    = (const float*)d_in[0];
    const float* mask = (const float*)d_in[1];
    const float* Wq   = (const float*)d_in[2];
    const float* bq   = (const float*)d_in[3];
    const float* Wk   = (const float*)d_in[4];
    const float* bk   = (const float*)d_in[5];
    const float* Wv   = (const float*)d_in[6];
    const float* bv   = (const float*)d_in[7];
    const float* Wo   = (const float*)d_in[8];
    const float* bo   = (const float*)d_in[9];
    const float* lng  = (const float*)d_in[10];
    const float* lnb  = (const float*)d_in[11];
    float* out = (float*)d_out;

    float* op;
    __nv_bfloat16 *ehi, *elo, *qh, *ql, *kh, *kl, *vh, *vl, *athi, *atlo, *wth, *wtl;
    cudaGetSymbolAddress((void**)&op,   g_o);
    cudaGetSymbolAddress((void**)&ehi,  g_ehi);
    cudaGetSymbolAddress((void**)&elo,  g_elo);
    cudaGetSymbolAddress((void**)&qh,   g_qh);
    cudaGetSymbolAddress((void**)&ql,   g_ql);
    cudaGetSymbolAddress((void**)&kh,   g_kh);
    cudaGetSymbolAddress((void**)&kl,   g_kl);
    cudaGetSymbolAddress((void**)&vh,   g_vh);
    cudaGetSymbolAddress((void**)&vl,   g_vl);
    cudaGetSymbolAddress((void**)&athi, g_athi);
    cudaGetSymbolAddress((void**)&atlo, g_atlo);
    cudaGetSymbolAddress((void**)&wth,  g_wthi);
    cudaGetSymbolAddress((void**)&wtl,  g_wtlo);

    cudaFuncSetAttribute(gemm_mma_kernel,
                         cudaFuncAttributeMaxDynamicSharedMemorySize, GEMM_SMEM);
    cudaFuncSetAttribute(flash_mma_kernel,
                         cudaFuncAttributeMaxDynamicSharedMemorySize, FLASH_SMEM);

    // 0) precision splits
    split_bf16_kernel<<<4096, 256>>>(E, ehi, elo, MDIM * NDIM / 4);
    wtrans_kernel<<<dim3(32, 32, 4), 256>>>(Wq, Wk, Wv, Wo, wth, wtl);

    // 1) fused QKV projections -> bf16 hi/lo directly
    gemm_mma_kernel<<<dim3(8, 32, 3), 256, GEMM_SMEM>>>(
        ehi, elo, wth, wtl, 0, bq, bk, bv,
        nullptr, nullptr, nullptr, nullptr,
        qh, kh, vh, ql, kl, vl, 1);

    // 2) flash attention on HMMA (S = Q@V^T/4 + mask, A = P@K)
    flash_mma_kernel<<<dim3(16, 32), 256, FLASH_SMEM>>>(
        qh, ql, kh, kl, vh, vl, mask, athi, atlo);

    // 3) output projection + bias + residual -> fp32
    gemm_mma_kernel<<<dim3(8, 32, 1), 256, GEMM_SMEM>>>(
        athi, atlo, wth, wtl, 3, bo, bo, bo,
        op, op, op, E,
        nullptr, nullptr, nullptr, nullptr, nullptr, nullptr, 0);

    // 4) layernorm
    ln_kernel<<<4096, 256>>>(op, lng, lnb, out);
}

// round 16
// speedup vs baseline: 2.3918x; 1.0354x over previous
#include <cuda_runtime.h>
#include <cuda_bf16.h>
#include <cstdint>

// ===========================================================================
// BERT attention block. R15: all tensor-core (mma.sync bf16 x3-term fp32
// emulation). Flash: 128-thread CTAs (2/SM, phase overlap), all-poly exp.
//   B=2, L=2048, H=1024, NH=16, D=64
// ===========================================================================

typedef unsigned long long u64;

__device__ __forceinline__ u64 pack2(float lo, float hi) {
    u64 r; asm("mov.b64 %0, {%1, %2};" : "=l"(r) : "f"(lo), "f"(hi)); return r;
}
__device__ __forceinline__ float2 unpack2(u64 v) {
    float2 f; asm("mov.b64 {%0, %1}, %2;" : "=f"(f.x), "=f"(f.y) : "l"(v)); return f;
}
__device__ __forceinline__ u64 fma2v(u64 a, u64 b, u64 c) {
    u64 d; asm("fma.rn.f32x2 %0, %1, %2, %3;" : "=l"(d) : "l"(a), "l"(b), "l"(c)); return d;
}
__device__ __forceinline__ u64 add2v(u64 a, u64 b) {
    u64 d; asm("add.rn.f32x2 %0, %1, %2;" : "=l"(d) : "l"(a), "l"(b)); return d;
}
__device__ __forceinline__ float ex2f(float x) {
    float y; asm("ex2.approx.f32 %0, %1;" : "=f"(y) : "f"(x)); return y;
}
__device__ __forceinline__ uint32_t smem_to_u32(const void* p) {
    uint32_t a;
    asm("{ .reg .u64 t; cvta.to.shared.u64 t, %1; cvt.u32.u64 %0, t; }"
        : "=r"(a) : "l"(p));
    return a;
}

// ---- mma.sync building blocks (sm_80+, valid on base sm_103) --------------
__device__ __forceinline__ void ldmx4(uint32_t* r, uint32_t addr) {
    asm volatile("ldmatrix.sync.aligned.m8n8.x4.shared.b16 {%0,%1,%2,%3}, [%4];"
                 : "=r"(r[0]), "=r"(r[1]), "=r"(r[2]), "=r"(r[3]) : "r"(addr));
}
__device__ __forceinline__ void ldmx2(uint32_t* r, uint32_t addr) {
    asm volatile("ldmatrix.sync.aligned.m8n8.x2.shared.b16 {%0,%1}, [%2];"
                 : "=r"(r[0]), "=r"(r[1]) : "r"(addr));
}
__device__ __forceinline__ void ldmx2t(uint32_t* r, uint32_t addr) {
    asm volatile("ldmatrix.sync.aligned.m8n8.x2.trans.shared.b16 {%0,%1}, [%2];"
                 : "=r"(r[0]), "=r"(r[1]) : "r"(addr));
}
__device__ __forceinline__ void mma_bf16(float* c, const uint32_t* a, const uint32_t* b) {
    asm volatile("mma.sync.aligned.m16n8k16.row.col.f32.bf16.bf16.f32 "
                 "{%0,%1,%2,%3}, {%4,%5,%6,%7}, {%8,%9}, {%0,%1,%2,%3};"
                 : "+f"(c[0]), "+f"(c[1]), "+f"(c[2]), "+f"(c[3])
                 : "r"(a[0]), "r"(a[1]), "r"(a[2]), "r"(a[3]), "r"(b[0]), "r"(b[1]));
}
#define CP_ASYNC16(dst, src) \
    asm volatile("cp.async.cg.shared.global [%0], [%1], 16;" :: "r"(dst), "l"(src))
#define CP_COMMIT() asm volatile("cp.async.commit_group;" ::: "memory")
#define CP_WAIT1()  asm volatile("cp.async.wait_group 1;" ::: "memory")
#define CP_WAIT0()  asm volatile("cp.async.wait_group 0;" ::: "memory")

#define MDIM 4096
#define NDIM 1024
#define KDIM 1024
#define LSEQ 2048
#define HEADD 64

// fast exp2: magic-round + deg-5 poly on f in [-0.5, 0.5], packed f32x2
__device__ __forceinline__ void exp2pair(float t0, float t1, float& y0, float& y1) {
    t0 = fmaxf(t0, -24.f); t1 = fmaxf(t1, -24.f);
    const float MG = 12582912.f;                  // 2^23 + 2^22
    u64 t2  = pack2(t0, t1);
    u64 fn2 = add2v(t2, pack2(MG, MG));           // round-to-nearest int in mantissa
    u64 n2  = add2v(fn2, pack2(-MG, -MG));
    u64 f2  = fma2v(n2, pack2(-1.f, -1.f), t2);   // f = t - n, in [-0.5, 0.5]
    u64 P   = pack2(1.33335581e-3f, 1.33335581e-3f);
    P = fma2v(P, f2, pack2(9.61812911e-3f, 9.61812911e-3f));
    P = fma2v(P, f2, pack2(5.55041087e-2f, 5.55041087e-2f));
    P = fma2v(P, f2, pack2(2.40226507e-1f, 2.40226507e-1f));
    P = fma2v(P, f2, pack2(6.93147182e-1f, 6.93147182e-1f));
    P = fma2v(P, f2, pack2(1.f, 1.f));
    float2 fn = unpack2(fn2), pp = unpack2(P);
    y0 = __int_as_float(__float_as_int(pp.x) + (__float_as_int(fn.x) << 23));
    y1 = __int_as_float(__float_as_int(pp.y) + (__float_as_int(fn.y) << 23));
}

__device__ __forceinline__ void packsplit(float x, float y, uint32_t& hi, uint32_t& lo) {
    __nv_bfloat16 hx = __float2bfloat16_rn(x), hy = __float2bfloat16_rn(y);
    __nv_bfloat16 lx = __float2bfloat16_rn(x - __bfloat162float(hx));
    __nv_bfloat16 ly = __float2bfloat16_rn(y - __bfloat162float(hy));
    __nv_bfloat162 h2(hx, hy), l2(lx, ly);
    hi = *(uint32_t*)&h2; lo = *(uint32_t*)&l2;
}

// GEMM smem geometry (row stride 112B: conflict-free ldmatrix)
#define TROWB   112
#define TILEB   (128 * TROWB)
#define STAGEB  (4 * TILEB)
#define GEMM_SMEM (2 * STAGEB)      // 114688

// Flash smem geometry (64-elem rows padded to 72 = 144B), 64-row tiles
#define FROWB   144
#define QTILEB  (64 * FROWB)        // 9216
#define KVTILEB (64 * FROWB)        // 9216
#define FSTAGEB (4 * KVTILEB)       // 36864
#define FLASH_SMEM (2 * QTILEB + 2 * FSTAGEB)   // 92160

// ---------------- scratch (__device__ globals; no allocation) --------------
__device__ float g_o[MDIM * NDIM];
__device__ __nv_bfloat16 g_ehi[MDIM * NDIM];
__device__ __nv_bfloat16 g_elo[MDIM * NDIM];
__device__ __nv_bfloat16 g_qh[MDIM * NDIM];
__device__ __nv_bfloat16 g_ql[MDIM * NDIM];
__device__ __nv_bfloat16 g_kh[MDIM * NDIM];
__device__ __nv_bfloat16 g_kl[MDIM * NDIM];
__device__ __nv_bfloat16 g_vh[MDIM * NDIM];
__device__ __nv_bfloat16 g_vl[MDIM * NDIM];
__device__ __nv_bfloat16 g_athi[MDIM * NDIM];
__device__ __nv_bfloat16 g_atlo[MDIM * NDIM];
__device__ __nv_bfloat16 g_wthi[4 * NDIM * KDIM];
__device__ __nv_bfloat16 g_wtlo[4 * NDIM * KDIM];

// ---------------------------------------------------------------------------
// split fp32 -> (hi, lo) bf16
// ---------------------------------------------------------------------------
__global__ __launch_bounds__(256)
void split_bf16_kernel(const float* __restrict__ x, __nv_bfloat16* __restrict__ hi,
                       __nv_bfloat16* __restrict__ lo, int n4)
{
    int i = blockIdx.x * blockDim.x + threadIdx.x;
    if (i >= n4) return;
    float4 v = ((const float4*)x)[i];
    uint32_t h0, l0, h1, l1;
    packsplit(v.x, v.y, h0, l0);
    packsplit(v.z, v.w, h1, l1);
    ((uint32_t*)hi)[i * 2 + 0] = h0; ((uint32_t*)hi)[i * 2 + 1] = h1;
    ((uint32_t*)lo)[i * 2 + 0] = l0; ((uint32_t*)lo)[i * 2 + 1] = l1;
}

// ---------------------------------------------------------------------------
// transpose + split the 4 weight matrices: Wt[z][n][k] = W_z[k][n] as hi/lo
// ---------------------------------------------------------------------------
__global__ __launch_bounds__(256)
void wtrans_kernel(const float* __restrict__ w0, const float* __restrict__ w1,
                   const float* __restrict__ w2, const float* __restrict__ w3,
                   __nv_bfloat16* __restrict__ hi, __nv_bfloat16* __restrict__ lo)
{
    __shared__ float t[32][33];
    const float* W = (blockIdx.z == 0) ? w0 : (blockIdx.z == 1) ? w1
                    : (blockIdx.z == 2) ? w2 : w3;
    int tx = threadIdx.x & 31, ty = threadIdx.x >> 5;
    int k0 = blockIdx.y * 32, n0 = blockIdx.x * 32;
#pragma unroll
    for (int i = 0; i < 4; i++)
        t[ty + i * 8][tx] = W[(size_t)(k0 + ty + i * 8) * NDIM + n0 + tx];
    __syncthreads();
    size_t base = (size_t)blockIdx.z * NDIM * KDIM;
#pragma unroll
    for (int i = 0; i < 4; i++) {
        float v = t[tx][ty + i * 8];
        __nv_bfloat16 h = __float2bfloat16_rn(v);
        __nv_bfloat16 l = __float2bfloat16_rn(v - __bfloat162float(h));
        size_t idx = base + (size_t)(n0 + ty + i * 8) * KDIM + k0 + tx;
        hi[idx] = h; lo[idx] = l;
    }
}

// ---------------------------------------------------------------------------
// HMMA GEMM: O = A[M,K] @ Wt[z][N,K]^T + bias (+resid or bf16 hi/lo out).
// CTA tile 128x128, 8 warps (warp tile 64x32), K-step 32, cp.async 2-stage.
// ---------------------------------------------------------------------------
__device__ __forceinline__ void issue_stage(uint32_t sbase,
    const __nv_bfloat16* __restrict__ Ah, const __nv_bfloat16* __restrict__ Al,
    const __nv_bfloat16* __restrict__ Bh, const __nv_bfloat16* __restrict__ Bl,
    int m0, int n0, int k0, int tid)
{
#pragma unroll
    for (int t = 0; t < 4; t++) {
        const __nv_bfloat16* g = (t == 0) ? Ah : (t == 1) ? Al : (t == 2) ? Bh : Bl;
        const int row0 = (t < 2) ? m0 : n0;
        const uint32_t st = sbase + t * TILEB;
#pragma unroll
        for (int u = 0; u < 2; u++) {
            int idx = tid + u * 256;
            int r = idx >> 2, c = idx & 3;
            const void* src = g + (size_t)(row0 + r) * KDIM + k0 + c * 8;
            CP_ASYNC16(st + r * TROWB + c * 16, src);
        }
    }
    CP_COMMIT();
}

__global__ __launch_bounds__(256, 1)
void gemm_mma_kernel(const __nv_bfloat16* __restrict__ Ah, const __nv_bfloat16* __restrict__ Al,
                     const __nv_bfloat16* __restrict__ Wh, const __nv_bfloat16* __restrict__ Wl,
                     int wbase,
                     const float* __restrict__ b0, const float* __restrict__ b1,
                     const float* __restrict__ b2,
                     float* __restrict__ O0, float* __restrict__ O1, float* __restrict__ O2,
                     const float* __restrict__ resid,
                     __nv_bfloat16* __restrict__ H0, __nv_bfloat16* __restrict__ H1,
                     __nv_bfloat16* __restrict__ H2,
                     __nv_bfloat16* __restrict__ L0, __nv_bfloat16* __restrict__ L1,
                     __nv_bfloat16* __restrict__ L2, int obf)
{
    extern __shared__ char smem[];
    const uint32_t sb = smem_to_u32(smem);
    const int tid = threadIdx.x, lane = tid & 31, wid = tid >> 5;
    const int wm = wid >> 2, wn = wid & 3;
    const int m0 = blockIdx.y * 128, n0 = blockIdx.x * 128, z = blockIdx.z;
    const float* bias = (z == 0) ? b0 : (z == 1) ? b1 : b2;
    const __nv_bfloat16* WhS = Wh + (size_t)(wbase + z) * NDIM * KDIM;
    const __nv_bfloat16* WlS = Wl + (size_t)(wbase + z) * NDIM * KDIM;

    float acc[4][4][4];
#pragma unroll
    for (int i = 0; i < 4; i++)
#pragma unroll
        for (int j = 0; j < 4; j++)
#pragma unroll
            for (int q = 0; q < 4; q++) acc[i][j][q] = 0.f;

    const uint32_t aoff = (uint32_t)((wm * 64 + (lane & 15)) * TROWB + ((lane >> 4) << 3) * 2);
    const uint32_t boff = (uint32_t)((wn * 32 + (lane & 7)) * TROWB + (((lane >> 3) & 1) << 3) * 2);

    issue_stage(sb, Ah, Al, WhS, WlS, m0, n0, 0, tid);

    const int NIT = KDIM / 32;
    for (int it = 0; it < NIT; it++) {
        if (it + 1 < NIT) {
            issue_stage(sb + ((it + 1) & 1) * STAGEB, Ah, Al, WhS, WlS,
                        m0, n0, (it + 1) * 32, tid);
            CP_WAIT1();
        } else {
            CP_WAIT0();
        }
        __syncthreads();

        const uint32_t sA = sb + (it & 1) * STAGEB;
        const uint32_t sAl_ = sA + TILEB;
        const uint32_t sBh_ = sA + 2 * TILEB;
        const uint32_t sBl_ = sA + 3 * TILEB;

#pragma unroll
        for (int kk = 0; kk < 2; kk++) {
            const uint32_t ko = kk * 32;
            uint32_t ah[4][4], al[4][4], bh[4][2], bl[4][2];
#pragma unroll
            for (int i = 0; i < 4; i++) ldmx4(ah[i], sA   + aoff + i * (16 * TROWB) + ko);
#pragma unroll
            for (int i = 0; i < 4; i++) ldmx4(al[i], sAl_ + aoff + i * (16 * TROWB) + ko);
#pragma unroll
            for (int j = 0; j < 4; j++) ldmx2(bh[j], sBh_ + boff + j * (8 * TROWB) + ko);
#pragma unroll
            for (int j = 0; j < 4; j++) ldmx2(bl[j], sBl_ + boff + j * (8 * TROWB) + ko);
#pragma unroll
            for (int i = 0; i < 4; i++)
#pragma unroll
                for (int j = 0; j < 4; j++) {
                    mma_bf16(acc[i][j], ah[i], bh[j]);
                    mma_bf16(acc[i][j], ah[i], bl[j]);
                    mma_bf16(acc[i][j], al[i], bh[j]);
                }
        }
        __syncthreads();
    }

    const int r0 = lane >> 2, c0 = (lane & 3) * 2;
    if (obf) {
        __nv_bfloat16* Hp = (z == 0) ? H0 : (z == 1) ? H1 : H2;
        __nv_bfloat16* Lp = (z == 0) ? L0 : (z == 1) ? L1 : L2;
#pragma unroll
        for (int i = 0; i < 4; i++) {
#pragma unroll
            for (int half = 0; half < 2; half++) {
                const int row = m0 + wm * 64 + i * 16 + r0 + half * 8;
#pragma unroll
                for (int j = 0; j < 4; j++) {
                    const int col = n0 + wn * 32 + j * 8 + c0;
                    float vx = acc[i][j][half * 2 + 0] + bias[col];
                    float vy = acc[i][j][half * 2 + 1] + bias[col + 1];
                    uint32_t hp, lp;
                    packsplit(vx, vy, hp, lp);
                    *(uint32_t*)&Hp[(size_t)row * NDIM + col] = hp;
                    *(uint32_t*)&Lp[(size_t)row * NDIM + col] = lp;
                }
            }
        }
    } else {
        float* O = (z == 0) ? O0 : (z == 1) ? O1 : O2;
#pragma unroll
        for (int i = 0; i < 4; i++) {
#pragma unroll
            for (int half = 0; half < 2; half++) {
                const int row = m0 + wm * 64 + i * 16 + r0 + half * 8;
                float* op = O + (size_t)row * NDIM;
                const float* rp = resid ? resid + (size_t)row * NDIM : nullptr;
#pragma unroll
                for (int j = 0; j < 4; j++) {
                    const int col = n0 + wn * 32 + j * 8 + c0;
                    float vx = acc[i][j][half * 2 + 0] + bias[col];
                    float vy = acc[i][j][half * 2 + 1] + bias[col + 1];
                    if (rp) { vx += rp[col]; vy += rp[col + 1]; }
                    *(float2*)&op[col] = make_float2(vx, vy);
                }
            }
        }
    }
}

// ---------------------------------------------------------------------------
// Flash attention on HMMA. CTA = 64 q-rows x one (b,h), 128 threads (4 warps,
// 16 q-rows each) -> 92KB smem -> 2 CTAs/SM so softmax of one CTA overlaps
// the MMA burst of the other. All-poly exp (FFMA2); MUFU only for 2 corrs.
//   S = Q@V^T * 0.25 + mask (log2 domain); online softmax; attended += P@K.
// ---------------------------------------------------------------------------
__device__ __forceinline__ void f_load64(uint32_t dst, const __nv_bfloat16* __restrict__ g,
                                         int b, int r0, int h, int tid) {
#pragma unroll
    for (int u = 0; u < 4; u++) {
        int idx = tid + u * 128;
        int r = idx >> 3, c = idx & 7;
        const void* src = g + (size_t)(b * LSEQ + r0 + r) * NDIM + h * HEADD + c * 8;
        CP_ASYNC16(dst + r * FROWB + c * 16, src);
    }
}

__global__ __launch_bounds__(128, 2)
void flash_mma_kernel(const __nv_bfloat16* __restrict__ Qh, const __nv_bfloat16* __restrict__ Ql,
                      const __nv_bfloat16* __restrict__ Kh, const __nv_bfloat16* __restrict__ Kl,
                      const __nv_bfloat16* __restrict__ Vh, const __nv_bfloat16* __restrict__ Vl,
                      const float* __restrict__ maskg,
                      __nv_bfloat16* __restrict__ Ahi, __nv_bfloat16* __restrict__ Alo)
{
    extern __shared__ char smem[];
    const uint32_t sb = smem_to_u32(smem);
    const int tid = threadIdx.x, lane = tid & 31, wid = tid >> 5;
    const int b = blockIdx.y >> 4, h = blockIdx.y & 15;
    const int q0 = blockIdx.x * 64;

    const uint32_t sQh = sb, sQl = sb + QTILEB;
    const uint32_t stg = sb + 2 * QTILEB;

    f_load64(sQh, Qh, b, q0, h, tid);
    f_load64(sQl, Ql, b, q0, h, tid);
    CP_COMMIT();
    f_load64(stg + 0 * KVTILEB, Kh, b, 0, h, tid);
    f_load64(stg + 1 * KVTILEB, Kl, b, 0, h, tid);
    f_load64(stg + 2 * KVTILEB, Vh, b, 0, h, tid);
    f_load64(stg + 3 * KVTILEB, Vl, b, 0, h, tid);
    CP_COMMIT();

    float att[8][4];
#pragma unroll
    for (int j = 0; j < 8; j++)
#pragma unroll
        for (int q = 0; q < 4; q++) att[j][q] = 0.f;
    float m0r = -1e30f, m1r = -1e30f, l0r = 0.f, l1r = 0.f;

    uint32_t aqh[4][4], aql[4][4];
    const uint32_t aoffq = (wid * 16 + (lane & 15)) * FROWB + (lane >> 4) * 16;
    const uint32_t boffv = (lane & 7) * FROWB + ((lane >> 3) & 1) * 16;
    const uint32_t bofft = (lane & 15) * FROWB;
    const float CS = 0.25f * 1.44269504089f;       // 1/4 * log2(e)
    const float LOG2E = 1.44269504089f;

    for (int kt = 0; kt < 32; kt++) {
        const int k0 = kt * 64;
        if (kt + 1 < 32) {
            const uint32_t ns = stg + ((kt + 1) & 1) * FSTAGEB;
            f_load64(ns + 0 * KVTILEB, Kh, b, k0 + 64, h, tid);
            f_load64(ns + 1 * KVTILEB, Kl, b, k0 + 64, h, tid);
            f_load64(ns + 2 * KVTILEB, Vh, b, k0 + 64, h, tid);
            f_load64(ns + 3 * KVTILEB, Vl, b, k0 + 64, h, tid);
            CP_COMMIT();
            CP_WAIT1();
        } else {
            CP_WAIT0();
        }
        __syncthreads();

        if (kt == 0) {
#pragma unroll
            for (int kk = 0; kk < 4; kk++) {
                ldmx4(aqh[kk], sQh + aoffq + kk * 32);
                ldmx4(aql[kk], sQl + aoffq + kk * 32);
            }
        }
        const uint32_t ss = stg + (kt & 1) * FSTAGEB;
        const uint32_t sKh_ = ss, sKl_ = ss + KVTILEB;
        const uint32_t sVh_ = ss + 2 * KVTILEB, sVl_ = ss + 3 * KVTILEB;

        // ---- S = Q @ V^T (3-term)
        float s[8][4];
#pragma unroll
        for (int j = 0; j < 8; j++)
#pragma unroll
            for (int q = 0; q < 4; q++) s[j][q] = 0.f;
#pragma unroll
        for (int kk = 0; kk < 4; kk++) {
#pragma unroll
            for (int j = 0; j < 8; j++) {
                uint32_t bh2[2], bl2[2];
                ldmx2(bh2, sVh_ + boffv + j * (8 * FROWB) + kk * 32);
                ldmx2(bl2, sVl_ + boffv + j * (8 * FROWB) + kk * 32);
                mma_bf16(s[j], aqh[kk], bh2);
                mma_bf16(s[j], aqh[kk], bl2);
                mma_bf16(s[j], aql[kk], bh2);
            }
        }

        // ---- online softmax in log2 domain (all-poly exp)
        const float* mp = maskg + b * LSEQ + k0 + (lane & 3) * 2;
        float rm0 = -1e30f, rm1 = -1e30f;
#pragma unroll
        for (int j = 0; j < 8; j++) {
            float mk0 = __ldg(mp + j * 8) * LOG2E;
            float mk1 = __ldg(mp + j * 8 + 1) * LOG2E;
            s[j][0] = s[j][0] * CS + mk0; s[j][1] = s[j][1] * CS + mk1;
            s[j][2] = s[j][2] * CS + mk0; s[j][3] = s[j][3] * CS + mk1;
            rm0 = fmaxf(rm0, fmaxf(s[j][0], s[j][1]));
            rm1 = fmaxf(rm1, fmaxf(s[j][2], s[j][3]));
        }
        rm0 = fmaxf(rm0, __shfl_xor_sync(0xffffffffu, rm0, 1));
        rm0 = fmaxf(rm0, __shfl_xor_sync(0xffffffffu, rm0, 2));
        rm1 = fmaxf(rm1, __shfl_xor_sync(0xffffffffu, rm1, 1));
        rm1 = fmaxf(rm1, __shfl_xor_sync(0xffffffffu, rm1, 2));
        float mn0 = fmaxf(m0r, rm0), mn1 = fmaxf(m1r, rm1);
        float cr0 = ex2f(m0r - mn0), cr1 = ex2f(m1r - mn1);
        m0r = mn0; m1r = mn1;
        float rs0 = 0.f, rs1 = 0.f;
#pragma unroll
        for (int j = 0; j < 8; j++) {
            float p0, p1, p2, p3;
            exp2pair(s[j][0] - mn0, s[j][1] - mn0, p0, p1);
            exp2pair(s[j][2] - mn1, s[j][3] - mn1, p2, p3);
            s[j][0] = p0; s[j][1] = p1; s[j][2] = p2; s[j][3] = p3;
            rs0 += p0 + p1; rs1 += p2 + p3;
        }
        rs0 += __shfl_xor_sync(0xffffffffu, rs0, 1);
        rs0 += __shfl_xor_sync(0xffffffffu, rs0, 2);
        rs1 += __shfl_xor_sync(0xffffffffu, rs1, 1);
        rs1 += __shfl_xor_sync(0xffffffffu, rs1, 2);
        l0r = l0r * cr0 + rs0; l1r = l1r * cr1 + rs1;
#pragma unroll
        for (int j = 0; j < 8; j++) {
            att[j][0] *= cr0; att[j][1] *= cr0;
            att[j][2] *= cr1; att[j][3] *= cr1;
        }

        // ---- pack P into A-fragments (acc layout == A m16k16 layout)
        uint32_t pah[4][4], pal[4][4];
#pragma unroll
        for (int jp = 0; jp < 4; jp++) {
            packsplit(s[2 * jp][0],     s[2 * jp][1],     pah[jp][0], pal[jp][0]);
            packsplit(s[2 * jp][2],     s[2 * jp][3],     pah[jp][1], pal[jp][1]);
            packsplit(s[2 * jp + 1][0], s[2 * jp + 1][1], pah[jp][2], pal[jp][2]);
            packsplit(s[2 * jp + 1][2], s[2 * jp + 1][3], pah[jp][3], pal[jp][3]);
        }

        // ---- attended += P @ K (K row-major [key][d] -> B frags via ldmatrix.trans)
#pragma unroll
        for (int kp = 0; kp < 4; kp++) {
#pragma unroll
            for (int j = 0; j < 8; j++) {
                uint32_t bh2[2], bl2[2];
                ldmx2t(bh2, sKh_ + kp * (16 * FROWB) + bofft + j * 16);
                ldmx2t(bl2, sKl_ + kp * (16 * FROWB) + bofft + j * 16);
                mma_bf16(att[j], pah[kp], bh2);
                mma_bf16(att[j], pah[kp], bl2);
                mma_bf16(att[j], pal[kp], bh2);
            }
        }
        __syncthreads();   // all warps done with this stage before reuse
    }

    // ---- epilogue: attended / l -> bf16 hi/lo
    float inv0 = 1.f / l0r, inv1 = 1.f / l1r;
    const int rowA = q0 + wid * 16 + (lane >> 2), rowB = rowA + 8;
    const int colb = h * HEADD + (lane & 3) * 2;
#pragma unroll
    for (int j = 0; j < 8; j++) {
        int col = colb + j * 8;
        uint32_t hp, lp;
        packsplit(att[j][0] * inv0, att[j][1] * inv0, hp, lp);
        *(uint32_t*)&Ahi[(size_t)(b * LSEQ + rowA) * NDIM + col] = hp;
        *(uint32_t*)&Alo[(size_t)(b * LSEQ + rowA) * NDIM + col] = lp;
        packsplit(att[j][2] * inv1, att[j][3] * inv1, hp, lp);
        *(uint32_t*)&Ahi[(size_t)(b * LSEQ + rowB) * NDIM + col] = hp;
        *(uint32_t*)&Alo[(size_t)(b * LSEQ + rowB) * NDIM + col] = lp;
    }
}

// ---------------------------------------------------------------------------
// Row LayerNorm
// ---------------------------------------------------------------------------
__global__ __launch_bounds__(256)
void ln_kernel(const float* __restrict__ X, const float* __restrict__ gamma,
               const float* __restrict__ beta, float* __restrict__ out)
{
    __shared__ float red[8];
    const int row = blockIdx.x;
    const int tid = threadIdx.x;

    float4 x = *(const float4*)&X[(size_t)row * NDIM + tid * 4];
    float s = x.x + x.y + x.z + x.w;
#pragma unroll
    for (int o = 16; o >= 1; o >>= 1) s += __shfl_xor_sync(0xffffffffu, s, o);
    if ((tid & 31) == 0) red[tid >> 5] = s;
    __syncthreads();
    float tot = 0.f;
#pragma unroll
    for (int w = 0; w < 8; w++) tot += red[w];
    float mu = tot * (1.0f / 1024.0f);

    float d0 = x.x - mu, d1 = x.y - mu, d2 = x.z - mu, d3 = x.w - mu;
    float ss = d0 * d0 + d1 * d1 + d2 * d2 + d3 * d3;
#pragma unroll
    for (int o = 16; o >= 1; o >>= 1) ss += __shfl_xor_sync(0xffffffffu, ss, o);
    __syncthreads();
    if ((tid & 31) == 0) red[tid >> 5] = ss;
    __syncthreads();
    float tot2 = 0.f;
#pragma unroll
    for (int w = 0; w < 8; w++) tot2 += red[w];
    float var = tot2 * (1.0f / 1024.0f);
    float r = rsqrtf(var + 1e-12f);

    float4 g  = *(const float4*)&gamma[tid * 4];
    float4 bt = *(const float4*)&beta[tid * 4];
    float4 o4;
    o4.x = d0 * r * g.x + bt.x;
    o4.y = d1 * r * g.y + bt.y;
    o4.z = d2 * r * g.z + bt.z;
    o4.w = d3 * r * g.w + bt.w;
    *(float4*)&out[(size_t)row * NDIM + tid * 4] = o4;
}

// ---------------------------------------------------------------------------
extern "C" void kernel_launch(void* const* d_in, const int* in_sizes, int n_in,
                              void* d_out, int out_size)
{
    const float* E    = (const float*)d_in[0];
    const float* mask = (const float*)d_in[1];
    const float* Wq   = (const float*)d_in[2];
    const float* bq   = (const float*)d_in[3];
    const float* Wk   = (const float*)d_in[4];
    const float* bk   = (const float*)d_in[5];
    const float* Wv   = (const float*)d_in[6];
    const float* bv   = (const float*)d_in[7];
    const float* Wo   = (const float*)d_in[8];
    const float* bo   = (const float*)d_in[9];
    const float* lng  = (const float*)d_in[10];
    const float* lnb  = (const float*)d_in[11];
    float* out = (float*)d_out;

    float* op;
    __nv_bfloat16 *ehi, *elo, *qh, *ql, *kh, *kl, *vh, *vl, *athi, *atlo, *wth, *wtl;
    cudaGetSymbolAddress((void**)&op,   g_o);
    cudaGetSymbolAddress((void**)&ehi,  g_ehi);
    cudaGetSymbolAddress((void**)&elo,  g_elo);
    cudaGetSymbolAddress((void**)&qh,   g_qh);
    cudaGetSymbolAddress((void**)&ql,   g_ql);
    cudaGetSymbolAddress((void**)&kh,   g_kh);
    cudaGetSymbolAddress((void**)&kl,   g_kl);
    cudaGetSymbolAddress((void**)&vh,   g_vh);
    cudaGetSymbolAddress((void**)&vl,   g_vl);
    cudaGetSymbolAddress((void**)&athi, g_athi);
    cudaGetSymbolAddress((void**)&atlo, g_atlo);
    cudaGetSymbolAddress((void**)&wth,  g_wthi);
    cudaGetSymbolAddress((void**)&wtl,  g_wtlo);

    cudaFuncSetAttribute(gemm_mma_kernel,
                         cudaFuncAttributeMaxDynamicSharedMemorySize, GEMM_SMEM);
    cudaFuncSetAttribute(flash_mma_kernel,
                         cudaFuncAttributeMaxDynamicSharedMemorySize, FLASH_SMEM);

    // 0) precision splits
    split_bf16_kernel<<<4096, 256>>>(E, ehi, elo, MDIM * NDIM / 4);
    wtrans_kernel<<<dim3(32, 32, 4), 256>>>(Wq, Wk, Wv, Wo, wth, wtl);

    // 1) fused QKV projections -> bf16 hi/lo directly
    gemm_mma_kernel<<<dim3(8, 32, 3), 256, GEMM_SMEM>>>(
        ehi, elo, wth, wtl, 0, bq, bk, bv,
        nullptr, nullptr, nullptr, nullptr,
        qh, kh, vh, ql, kl, vl, 1);

    // 2) flash attention on HMMA (S = Q@V^T/4 + mask, A = P@K), 2 CTAs/SM
    flash_mma_kernel<<<dim3(32, 32), 128, FLASH_SMEM>>>(
        qh, ql, kh, kl, vh, vl, mask, athi, atlo);

    // 3) output projection + bias + residual -> fp32
    gemm_mma_kernel<<<dim3(8, 32, 1), 256, GEMM_SMEM>>>(
        athi, atlo, wth, wtl, 3, bo, bo, bo,
        op, op, op, E,
        nullptr, nullptr, nullptr, nullptr, nullptr, nullptr, 0);

    // 4) layernorm
    ln_kernel<<<4096, 256>>>(op, lng, lnb, out);
}